// round 14
// baseline (speedup 1.0000x reference)
#include <cuda_runtime.h>
#include <cuda_bf16.h>
#include <math.h>
#include <stdint.h>

#define Bb   8
#define Ss   256
#define Nn   512
#define Ii   32
#define HH   64
#define Oo   32
#define BS   (Bb*Ss)                 // 2048
#define RTOT (BS*Nn)                 // 1,048,576 rows
#define BN   (Bb*Nn)                 // 4096 GRU sequences

typedef unsigned long long ull;

// Scratch
__device__ uint32_t g_spb [(size_t)RTOT * Oo];  // 134 MB: packed (bf16 hi, bf16 lo)
__device__ float    g_tanh[(size_t)RTOT * Oo];
__device__ float    g_gi  [(size_t)RTOT * 96];  // [(b*256+s)*512+n][96]
__device__ __nv_bfloat16 g_adjh[Nn * Nn];
__device__ __nv_bfloat16 g_adjl[Nn * Nn];

__device__ __forceinline__ float warp_sum(float v) {
    #pragma unroll
    for (int o = 16; o > 0; o >>= 1) v += __shfl_xor_sync(0xffffffffu, v, o);
    return v;
}
__device__ __forceinline__ float sigmoid_f(float x) {
    return __fdividef(1.f, 1.f + __expf(-x));
}
__device__ __forceinline__ float tanh_f(float x) {
    float ax = fabsf(x);
    float e  = __expf(-2.f * ax);
    float t  = (1.f - e) * __fdividef(1.f, 1.f + e);
    return copysignf(t, x);
}
__device__ __forceinline__ float tf32_rna(float v) {
    uint32_t u; asm("cvt.rna.tf32.f32 %0,%1;" : "=r"(u) : "f"(v));
    return __uint_as_float(u);
}
__device__ __forceinline__ uint32_t as_u(float f) { return __float_as_uint(f); }
__device__ __forceinline__ float bf_hi(float v) {
    return __bfloat162float(__float2bfloat16_rn(v));
}
__device__ __forceinline__ uint32_t bfpack(float a, float b) {
    __nv_bfloat162 t = __floats2bfloat162_rn(a, b);
    return *reinterpret_cast<uint32_t*>(&t);
}
// packed (hi, lo) u32 for one fp32 value
__device__ __forceinline__ uint32_t pack_hl(float v) {
    float h = bf_hi(v);
    return bfpack(h, v - h);
}
__device__ __forceinline__ ull pack2(float lo, float hi) {
    ull r; asm("mov.b64 %0,{%1,%2};" : "=l"(r) : "f"(lo), "f"(hi)); return r;
}
__device__ __forceinline__ float2 unpack2(ull v) {
    float2 f; asm("mov.b64 {%0,%1},%2;" : "=f"(f.x), "=f"(f.y) : "l"(v)); return f;
}

struct F4 { float x, y, z, w; };
__device__ __forceinline__ void mma_tf32(F4& d,
    uint32_t a0, uint32_t a1, uint32_t a2, uint32_t a3, uint32_t b0, uint32_t b1)
{
    asm volatile(
        "mma.sync.aligned.m16n8k8.row.col.f32.tf32.tf32.f32 "
        "{%0,%1,%2,%3},{%4,%5,%6,%7},{%8,%9},{%0,%1,%2,%3};"
        : "+f"(d.x), "+f"(d.y), "+f"(d.z), "+f"(d.w)
        : "r"(a0), "r"(a1), "r"(a2), "r"(a3), "r"(b0), "r"(b1));
}
__device__ __forceinline__ void mma_bf16(F4& d,
    uint32_t a0, uint32_t a1, uint32_t a2, uint32_t a3, uint32_t b0, uint32_t b1)
{
    asm volatile(
        "mma.sync.aligned.m16n8k16.row.col.f32.bf16.bf16.f32 "
        "{%0,%1,%2,%3},{%4,%5,%6,%7},{%8,%9},{%0,%1,%2,%3};"
        : "+f"(d.x), "+f"(d.y), "+f"(d.z), "+f"(d.w)
        : "r"(a0), "r"(a1), "r"(a2), "r"(a3), "r"(b0), "r"(b1));
}
__device__ __forceinline__ void cp4(uint32_t dst, const float* src) {
    asm volatile("cp.async.ca.shared.global [%0], [%1], 4;" :: "r"(dst), "l"(src));
}

// ---------------------------------------------------------------------------
// K0: split adj into bf16 hi + bf16 residual
// ---------------------------------------------------------------------------
__global__ __launch_bounds__(256) void k0_split(
    const float* __restrict__ adj,
    __nv_bfloat16* __restrict__ hi, __nv_bfloat16* __restrict__ lo)
{
    int i = blockIdx.x * 256 + threadIdx.x;
    float v = adj[i];
    __nv_bfloat16 h = __float2bfloat16_rn(v);
    hi[i] = h;
    lo[i] = __float2bfloat16_rn(v - __bfloat162float(h));
}

// ---------------------------------------------------------------------------
// K1 (bf16 MMA): 2 row-tiles of 128 per block; weights staged once.
// NEW: stores sp as packed (bf16 hi, bf16 lo) u32 — k2 stages with PRMT only.
// ---------------------------------------------------------------------------
__global__ __launch_bounds__(256) void k1_mma(
    const float* __restrict__ x,  const float* __restrict__ W1,
    const float* __restrict__ b1, const float* __restrict__ g1,
    const float* __restrict__ be1,const float* __restrict__ W2,
    const float* __restrict__ b2, uint32_t* __restrict__ spb)
{
    __shared__ __align__(16) uint32_t W1fh[1536], W1fl[1536];
    __shared__ __align__(16) uint32_t W2fh[3072], W2fl[3072];
    __shared__ float2 b1p[32], g1p[32], be1p[32], b2p[16];

    int tid = threadIdx.x, lane = tid & 31, wid = tid >> 5;
    int r = lane >> 2, c = lane & 3;

    #pragma unroll
    for (int p = 0; p < 4; p++) {
        int i = p * 256 + tid;
        int kp = i >> 6, n = i & 63;
        float wa = W1[(2 * kp) * 64 + n], wb = W1[(2 * kp + 1) * 64 + n];
        float ha = bf_hi(wa), hb = bf_hi(wb);
        int kt = kp >> 3, kpl = kp & 7, half = kpl >> 2, cc = kpl & 3;
        int j = n >> 3, rr = n & 7;
        int idx = (kt * 2 + half) * 384 + (rr * 4 + cc) * 12 + j;
        W1fh[idx] = bfpack(ha, hb);
        W1fl[idx] = bfpack(wa - ha, wb - hb);
    }
    #pragma unroll
    for (int p = 0; p < 4; p++) {
        int i = p * 256 + tid;
        int kp = i >> 5, n = i & 31;
        float wa = W2[(2 * kp) * 32 + n], wb = W2[(2 * kp + 1) * 32 + n];
        float ha = bf_hi(wa), hb = bf_hi(wb);
        int kt = kp >> 3, kpl = kp & 7, half = kpl >> 2, cc = kpl & 3;
        int j = n >> 3, rr = n & 7;
        int idx = (kt * 2 + half) * 384 + (rr * 4 + cc) * 12 + j;
        W2fh[idx] = bfpack(ha, hb);
        W2fl[idx] = bfpack(wa - ha, wb - hb);
    }
    if (tid < 32) {
        b1p[tid]  = ((const float2*)b1)[tid];
        g1p[tid]  = ((const float2*)g1)[tid];
        be1p[tid] = ((const float2*)be1)[tid];
        if (tid < 16) b2p[tid] = ((const float2*)b2)[tid];
    }
    __syncthreads();

    for (int tile = 0; tile < 2; tile++) {
        size_t row0 = (size_t)blockIdx.x * 256 + (size_t)tile * 128;

        const float* xr  = x + (row0 + wid * 16 + r) * 32;
        const float* xr8 = xr + 8 * 32;
        float2 xa0[2], xa1[2], xa2[2], xa3[2];
        uint32_t A1h[2][4], A1l[2][4];
        #pragma unroll
        for (int kt = 0; kt < 2; kt++) {
            xa0[kt] = ((const float2*)xr)[kt * 8 + c];
            xa2[kt] = ((const float2*)xr)[kt * 8 + 4 + c];
            xa1[kt] = ((const float2*)xr8)[kt * 8 + c];
            xa3[kt] = ((const float2*)xr8)[kt * 8 + 4 + c];
            float h;
            h = bf_hi(xa0[kt].x); float h2 = bf_hi(xa0[kt].y);
            A1h[kt][0] = bfpack(h, h2); A1l[kt][0] = bfpack(xa0[kt].x - h, xa0[kt].y - h2);
            h = bf_hi(xa1[kt].x); h2 = bf_hi(xa1[kt].y);
            A1h[kt][1] = bfpack(h, h2); A1l[kt][1] = bfpack(xa1[kt].x - h, xa1[kt].y - h2);
            h = bf_hi(xa2[kt].x); h2 = bf_hi(xa2[kt].y);
            A1h[kt][2] = bfpack(h, h2); A1l[kt][2] = bfpack(xa2[kt].x - h, xa2[kt].y - h2);
            h = bf_hi(xa3[kt].x); h2 = bf_hi(xa3[kt].y);
            A1h[kt][3] = bfpack(h, h2); A1l[kt][3] = bfpack(xa3[kt].x - h, xa3[kt].y - h2);
        }

        F4 acc1[8];
        #pragma unroll
        for (int j = 0; j < 8; j++) { acc1[j].x = acc1[j].y = acc1[j].z = acc1[j].w = 0.f; }
        #pragma unroll
        for (int kt = 0; kt < 2; kt++) {
            uint32_t bh0[8], bh1[8], bl0[8], bl1[8];
            {
                const uint4* p0 = (const uint4*)&W1fh[(kt * 2 + 0) * 384 + lane * 12];
                const uint4* p1 = (const uint4*)&W1fh[(kt * 2 + 1) * 384 + lane * 12];
                const uint4* q0 = (const uint4*)&W1fl[(kt * 2 + 0) * 384 + lane * 12];
                const uint4* q1 = (const uint4*)&W1fl[(kt * 2 + 1) * 384 + lane * 12];
                uint4 t;
                t = p0[0]; bh0[0]=t.x; bh0[1]=t.y; bh0[2]=t.z; bh0[3]=t.w;
                t = p0[1]; bh0[4]=t.x; bh0[5]=t.y; bh0[6]=t.z; bh0[7]=t.w;
                t = p1[0]; bh1[0]=t.x; bh1[1]=t.y; bh1[2]=t.z; bh1[3]=t.w;
                t = p1[1]; bh1[4]=t.x; bh1[5]=t.y; bh1[6]=t.z; bh1[7]=t.w;
                t = q0[0]; bl0[0]=t.x; bl0[1]=t.y; bl0[2]=t.z; bl0[3]=t.w;
                t = q0[1]; bl0[4]=t.x; bl0[5]=t.y; bl0[6]=t.z; bl0[7]=t.w;
                t = q1[0]; bl1[0]=t.x; bl1[1]=t.y; bl1[2]=t.z; bl1[3]=t.w;
                t = q1[1]; bl1[4]=t.x; bl1[5]=t.y; bl1[6]=t.z; bl1[7]=t.w;
            }
            #pragma unroll
            for (int j = 0; j < 8; j++) {
                mma_bf16(acc1[j], A1h[kt][0], A1h[kt][1], A1h[kt][2], A1h[kt][3], bh0[j], bh1[j]);
                mma_bf16(acc1[j], A1l[kt][0], A1l[kt][1], A1l[kt][2], A1l[kt][3], bh0[j], bh1[j]);
                mma_bf16(acc1[j], A1h[kt][0], A1h[kt][1], A1h[kt][2], A1h[kt][3], bl0[j], bl1[j]);
            }
        }

        float s0 = 0.f, q0s = 0.f, s1 = 0.f, q1s = 0.f;
        #pragma unroll
        for (int j = 0; j < 8; j++) {
            float2 b = b1p[c + 4 * j];
            acc1[j].x += b.x; acc1[j].y += b.y; acc1[j].z += b.x; acc1[j].w += b.y;
            s0 += acc1[j].x + acc1[j].y;
            q0s += acc1[j].x * acc1[j].x + acc1[j].y * acc1[j].y;
            s1 += acc1[j].z + acc1[j].w;
            q1s += acc1[j].z * acc1[j].z + acc1[j].w * acc1[j].w;
        }
        s0 += __shfl_xor_sync(0xffffffffu, s0, 1); s0 += __shfl_xor_sync(0xffffffffu, s0, 2);
        q0s += __shfl_xor_sync(0xffffffffu, q0s, 1); q0s += __shfl_xor_sync(0xffffffffu, q0s, 2);
        s1 += __shfl_xor_sync(0xffffffffu, s1, 1); s1 += __shfl_xor_sync(0xffffffffu, s1, 2);
        q1s += __shfl_xor_sync(0xffffffffu, q1s, 1); q1s += __shfl_xor_sync(0xffffffffu, q1s, 2);
        float mu0 = s0 * (1.f / 64.f), mu1 = s1 * (1.f / 64.f);
        float rstd0 = rsqrtf(fmaf(-mu0, mu0, q0s * (1.f / 64.f)) + 1e-5f);
        float rstd1 = rsqrtf(fmaf(-mu1, mu1, q1s * (1.f / 64.f)) + 1e-5f);
        #pragma unroll
        for (int j = 0; j < 8; j++) {
            float2 g = g1p[c + 4 * j], be = be1p[c + 4 * j];
            acc1[j].x = fmaxf(fmaf((acc1[j].x - mu0) * rstd0, g.x, be.x), 0.f);
            acc1[j].y = fmaxf(fmaf((acc1[j].y - mu0) * rstd0, g.y, be.y), 0.f);
            acc1[j].z = fmaxf(fmaf((acc1[j].z - mu1) * rstd1, g.x, be.x), 0.f);
            acc1[j].w = fmaxf(fmaf((acc1[j].w - mu1) * rstd1, g.y, be.y), 0.f);
        }

        uint32_t A2h[4][4], A2l[4][4];
        #pragma unroll
        for (int kt = 0; kt < 4; kt++) {
            F4 e = acc1[2 * kt], o = acc1[2 * kt + 1];
            float h;
            h = bf_hi(e.x); float h2 = bf_hi(e.y);
            A2h[kt][0] = bfpack(h, h2); A2l[kt][0] = bfpack(e.x - h, e.y - h2);
            h = bf_hi(e.z); h2 = bf_hi(e.w);
            A2h[kt][1] = bfpack(h, h2); A2l[kt][1] = bfpack(e.z - h, e.w - h2);
            h = bf_hi(o.x); h2 = bf_hi(o.y);
            A2h[kt][2] = bfpack(h, h2); A2l[kt][2] = bfpack(o.x - h, o.y - h2);
            h = bf_hi(o.z); h2 = bf_hi(o.w);
            A2h[kt][3] = bfpack(h, h2); A2l[kt][3] = bfpack(o.z - h, o.w - h2);
        }

        F4 acc2[4];
        #pragma unroll
        for (int j = 0; j < 4; j++) { acc2[j].x = acc2[j].y = acc2[j].z = acc2[j].w = 0.f; }
        #pragma unroll
        for (int kt = 0; kt < 4; kt++) {
            uint4 h0 = *(const uint4*)&W2fh[(kt * 2 + 0) * 384 + lane * 12];
            uint4 h1 = *(const uint4*)&W2fh[(kt * 2 + 1) * 384 + lane * 12];
            uint4 l0 = *(const uint4*)&W2fl[(kt * 2 + 0) * 384 + lane * 12];
            uint4 l1 = *(const uint4*)&W2fl[(kt * 2 + 1) * 384 + lane * 12];
            uint32_t bh0[4] = {h0.x, h0.y, h0.z, h0.w};
            uint32_t bh1[4] = {h1.x, h1.y, h1.z, h1.w};
            uint32_t bl0[4] = {l0.x, l0.y, l0.z, l0.w};
            uint32_t bl1[4] = {l1.x, l1.y, l1.z, l1.w};
            #pragma unroll
            for (int j = 0; j < 4; j++) {
                mma_bf16(acc2[j], A2h[kt][0], A2h[kt][1], A2h[kt][2], A2h[kt][3], bh0[j], bh1[j]);
                mma_bf16(acc2[j], A2l[kt][0], A2l[kt][1], A2l[kt][2], A2l[kt][3], bh0[j], bh1[j]);
                mma_bf16(acc2[j], A2h[kt][0], A2h[kt][1], A2h[kt][2], A2h[kt][3], bl0[j], bl1[j]);
            }
        }

        size_t orow = row0 + wid * 16 + r;
        #pragma unroll
        for (int j = 0; j < 4; j++) {
            float2 b = b2p[4 * j + c];
            int kth = j >> 1;
            float2 rx0 = (j & 1) ? xa2[kth] : xa0[kth];
            float2 rx1 = (j & 1) ? xa3[kth] : xa1[kth];
            float v00 = acc2[j].x + b.x + rx0.x, v01 = acc2[j].y + b.y + rx0.y;
            float v10 = acc2[j].z + b.x + rx1.x, v11 = acc2[j].w + b.y + rx1.y;
            uint2 s0v = { pack_hl(v00), pack_hl(v01) };
            uint2 s1v = { pack_hl(v10), pack_hl(v11) };
            *(uint2*)&spb[orow * 32 + 8 * j + 2 * c]       = s0v;
            *(uint2*)&spb[(orow + 8) * 32 + 8 * j + 2 * c] = s1v;
        }
    }
}

// ---------------------------------------------------------------------------
// K2 (bf16 m16n8k16, 3-pass). NEW: sp comes pre-split as packed (hi,lo) u32;
// B staging is 2x LDG.128 + 8x PRMT + 8x STS (no cvt/sub/pack).
// ---------------------------------------------------------------------------
__global__ __launch_bounds__(256) void k2_mma(
    const __nv_bfloat16* __restrict__ adjh, const __nv_bfloat16* __restrict__ adjl,
    const uint32_t* __restrict__ spb, float* __restrict__ out)
{
    __shared__ __align__(16) uint32_t Ahs[2048], Als[2048];
    __shared__ __align__(16) uint32_t Bhs[2560], Bls[2560];

    int tid = threadIdx.x, lane = tid & 31, wid = tid >> 5;
    int n0  = blockIdx.x * 128;
    int bs0 = blockIdx.y * 4;
    int r = lane >> 2, c = lane & 3;

    F4 acc[4][4];
    #pragma unroll
    for (int u = 0; u < 4; u++)
        #pragma unroll
        for (int j = 0; j < 4; j++) { acc[u][j].x = acc[u][j].y = acc[u][j].z = acc[u][j].w = 0.f; }

    for (int mc = 0; mc < 512; mc += 32) {
        __syncthreads();
        #pragma unroll
        for (int p = 0; p < 2; p++) {
            int i = p * 256 + tid;
            int n = i >> 2, seg = i & 3;
            size_t boff = ((size_t)(n0 + n) * 512 + mc) * 2 + seg * 16;
            uint4 vh = *(const uint4*)((const char*)adjh + boff);
            uint4 vl = *(const uint4*)((const char*)adjl + boff);
            int w = n >> 4, rr = n & 15, rf = rr & 7, rh = rr >> 3, kt = seg >> 1;
            int base = (w * 2 + kt) * 128 + rf * 16;
            uint32_t ah[4] = {vh.x, vh.y, vh.z, vh.w};
            uint32_t al[4] = {vl.x, vl.y, vl.z, vl.w};
            #pragma unroll
            for (int u = 0; u < 4; u++) {
                int kpl = (seg & 1) * 4 + u;
                int cc = kpl & 3, side = kpl >> 2;
                Ahs[base + cc * 4 + side * 2 + rh] = ah[u];
                Als[base + cc * 4 + side * 2 + rh] = al[u];
            }
        }
        #pragma unroll
        for (int p = 0; p < 2; p++) {
            int u = p * 2 + (tid >> 7);
            int rem = tid & 127;
            int kp = rem >> 3, q = rem & 7, col0 = q * 4;
            const uint32_t* s0 = &spb[((size_t)(bs0 + u) * 512 + mc + 2 * kp) * 32 + col0];
            uint4 A  = *(const uint4*)s0;
            uint4 Bv = *(const uint4*)(s0 + 32);
            int kt = kp >> 3, kpl = kp & 7, half = kpl >> 2, cc = kpl & 3;
            int bb = ((u * 2 + kt) * 2 + half) * 160 + cc * 40;
            uint32_t av[4] = {A.x, A.y, A.z, A.w};
            uint32_t bv[4] = {Bv.x, Bv.y, Bv.z, Bv.w};
            #pragma unroll
            for (int i = 0; i < 4; i++) {
                int col = col0 + i, j = col >> 3, rr = col & 7;
                Bhs[bb + rr * 4 + j] = __byte_perm(av[i], bv[i], 0x5410);
                Bls[bb + rr * 4 + j] = __byte_perm(av[i], bv[i], 0x7632);
            }
        }
        __syncthreads();

        #pragma unroll
        for (int kt = 0; kt < 2; kt++) {
            uint4 Ah4 = *(const uint4*)&Ahs[(wid * 2 + kt) * 128 + lane * 4];
            uint4 Al4 = *(const uint4*)&Als[(wid * 2 + kt) * 128 + lane * 4];
            #pragma unroll
            for (int u = 0; u < 4; u++) {
                int bb = ((u * 2 + kt) * 2) * 160 + c * 40 + r * 4;
                uint4 h0 = *(const uint4*)&Bhs[bb];
                uint4 h1 = *(const uint4*)&Bhs[bb + 160];
                uint4 l0 = *(const uint4*)&Bls[bb];
                uint4 l1 = *(const uint4*)&Bls[bb + 160];
                uint32_t bh0[4] = {h0.x, h0.y, h0.z, h0.w};
                uint32_t bh1[4] = {h1.x, h1.y, h1.z, h1.w};
                uint32_t bl0[4] = {l0.x, l0.y, l0.z, l0.w};
                uint32_t bl1[4] = {l1.x, l1.y, l1.z, l1.w};
                #pragma unroll
                for (int j = 0; j < 4; j++) {
                    mma_bf16(acc[u][j], Ah4.x, Ah4.y, Ah4.z, Ah4.w, bh0[j], bh1[j]);
                    mma_bf16(acc[u][j], Al4.x, Al4.y, Al4.z, Al4.w, bh0[j], bh1[j]);
                    mma_bf16(acc[u][j], Ah4.x, Ah4.y, Ah4.z, Ah4.w, bl0[j], bl1[j]);
                }
            }
        }
    }

    int c2 = c * 2;
    #pragma unroll
    for (int u = 0; u < 4; u++) {
        size_t bsrow = (size_t)(bs0 + u) * 512;
        #pragma unroll
        for (int j = 0; j < 4; j++) {
            int col  = j * 8 + c2;
            int row0 = n0 + wid * 16 + r;
            float2 v0 = { tanh_f(acc[u][j].x), tanh_f(acc[u][j].y) };
            float2 v1 = { tanh_f(acc[u][j].z), tanh_f(acc[u][j].w) };
            *(float2*)&out[(bsrow + row0)     * 32 + col] = v0;
            *(float2*)&out[(bsrow + row0 + 8) * 32 + col] = v1;
        }
    }
}

// ---------------------------------------------------------------------------
// K3 (tf32 3-pass, R8/R11 version): B fragment-pair prestage + 2 row-tiles.
// ---------------------------------------------------------------------------
#define K3_SMEM_FLOATS (2*4608 + 2*3168 + 96)

__global__ __launch_bounds__(256) void k3_mma(
    const float* __restrict__ tin, const float* __restrict__ g2,
    const float* __restrict__ be2, const float* __restrict__ w_ih,
    const float* __restrict__ b_ih, float* __restrict__ gi)
{
    extern __shared__ float smem[];
    float* Ah  = smem;
    float* Al  = Ah + 4608;
    float* Bfh = Al + 4608;
    float* Bfl = Bfh + 3168;
    float* bis = Bfl + 3168;

    int tid = threadIdx.x, lane = tid & 31, wid = tid >> 5;
    int r = lane >> 2, c = lane & 3;
    int mbase = wid * 16;

    #pragma unroll
    for (int p = 0; p < 12; p++) {
        int v = p * 256 + tid;
        int k = v & 31, col = v >> 5;
        float w = w_ih[col * 32 + k];
        float h = tf32_rna(w);
        int kt = k >> 3, cc = k & 3, reg = (k >> 2) & 1;
        int j = col >> 3, rr = col & 7;
        int addr = kt * 792 + j * 66 + (rr * 4 + cc) * 2 + reg;
        Bfh[addr] = h;
        Bfl[addr] = w - h;
    }
    if (tid < 96) bis[tid] = b_ih[tid];

    float g2v = g2[lane], be2v = be2[lane];

    for (int tile = 0; tile < 2; tile++) {
        size_t rr0 = (size_t)blockIdx.x * 256 + (size_t)tile * 128;
        if (tile) __syncthreads();

        #pragma unroll
        for (int q = 0; q < 16; q++) {
            int row = wid * 16 + q;
            float v = tin[(rr0 + row) * 32 + lane];
            float mu = warp_sum(v) * (1.f / 32.f);
            float d = v - mu;
            float var = warp_sum(d * d) * (1.f / 32.f);
            float ln = fmaf(d * rsqrtf(var + 1e-5f), g2v, be2v);
            float lh = tf32_rna(ln);
            Ah[row * 36 + lane] = lh;
            Al[row * 36 + lane] = ln - lh;
        }
        __syncthreads();

        F4 acc[12];
        #pragma unroll
        for (int j = 0; j < 12; j++) { acc[j].x = acc[j].y = acc[j].z = acc[j].w = 0.f; }

        #pragma unroll
        for (int kt = 0; kt < 4; kt++) {
            int kb = kt * 8;
            uint32_t ah0 = as_u(Ah[(mbase + r)     * 36 + kb + c]);
            uint32_t ah1 = as_u(Ah[(mbase + 8 + r) * 36 + kb + c]);
            uint32_t ah2 = as_u(Ah[(mbase + r)     * 36 + kb + 4 + c]);
            uint32_t ah3 = as_u(Ah[(mbase + 8 + r) * 36 + kb + 4 + c]);
            uint32_t al0 = as_u(Al[(mbase + r)     * 36 + kb + c]);
            uint32_t al1 = as_u(Al[(mbase + 8 + r) * 36 + kb + c]);
            uint32_t al2 = as_u(Al[(mbase + r)     * 36 + kb + 4 + c]);
            uint32_t al3 = as_u(Al[(mbase + 8 + r) * 36 + kb + 4 + c]);
            const float* bhp = &Bfh[kt * 792 + lane * 2];
            const float* blp = &Bfl[kt * 792 + lane * 2];
            #pragma unroll
            for (int j = 0; j < 12; j++) {
                float2 bh = *(const float2*)(bhp + j * 66);
                float2 bl = *(const float2*)(blp + j * 66);
                mma_tf32(acc[j], ah0, ah1, ah2, ah3, as_u(bh.x), as_u(bh.y));
                mma_tf32(acc[j], al0, al1, al2, al3, as_u(bh.x), as_u(bh.y));
                mma_tf32(acc[j], ah0, ah1, ah2, ah3, as_u(bl.x), as_u(bl.y));
            }
        }

        int c2 = c * 2;
        #pragma unroll
        for (int j = 0; j < 12; j++) {
            int col = j * 8 + c2;
            float2 bi = *(const float2*)&bis[col];
            size_t row0 = rr0 + mbase + r;
            float2 v0 = { acc[j].x + bi.x, acc[j].y + bi.y };
            float2 v1 = { acc[j].z + bi.x, acc[j].w + bi.y };
            *(float2*)&gi[row0 * 96 + col]       = v0;
            *(float2*)&gi[(row0 + 8) * 96 + col] = v1;
        }
    }
}

// ---------------------------------------------------------------------------
// K4 (R11 version): 2 sequences per warp, single wave.
// ---------------------------------------------------------------------------
__global__ __launch_bounds__(128, 4) void k4_gru(
    const float* __restrict__ gi, const float* __restrict__ w_hh,
    const float* __restrict__ b_hh, float* __restrict__ out)
{
    __shared__ float gbuf[4][8][192];

    int tid = threadIdx.x, lane = tid & 31, wr = tid >> 5;
    int p = blockIdx.x * 4 + wr;
    int bn = 2 * p;
    int b = bn >> 9, n = bn & 511;

    float w0[32], w1[32], w2[32];
    #pragma unroll
    for (int m = 0; m < 8; m++) {
        float4 a = ((const float4*)(w_hh + (size_t)lane * 32))[m];
        float4 cc = ((const float4*)(w_hh + (size_t)(lane + 32) * 32))[m];
        float4 d = ((const float4*)(w_hh + (size_t)(lane + 64) * 32))[m];
        w0[4*m+0]=a.x;  w0[4*m+1]=a.y;  w0[4*m+2]=a.z;  w0[4*m+3]=a.w;
        w1[4*m+0]=cc.x; w1[4*m+1]=cc.y; w1[4*m+2]=cc.z; w1[4*m+3]=cc.w;
        w2[4*m+0]=d.x;  w2[4*m+1]=d.y;  w2[4*m+2]=d.z;  w2[4*m+3]=d.w;
    }
    float bh0 = b_hh[lane], bh1 = b_hh[lane + 32], bh2 = b_hh[lane + 64];

    const size_t tstride = (size_t)512 * 96;
    const float* gA = gi + ((size_t)(b * 256) * 512 + n) * 96;

    #pragma unroll
    for (int s = 0; s < 7; s++) {
        const float* src = gA + (size_t)s * tstride;
        uint32_t d = (uint32_t)__cvta_generic_to_shared(&gbuf[wr][s][lane]);
        cp4(d,       src + lane);
        cp4(d + 128, src + lane + 32);
        cp4(d + 256, src + lane + 64);
        cp4(d + 384, src + lane + 96);
        cp4(d + 512, src + lane + 128);
        cp4(d + 640, src + lane + 160);
        asm volatile("cp.async.commit_group;" ::: "memory");
    }

    float hA = 0.f, hB = 0.f;
    ull hp = 0;
    float* outp = out + ((size_t)(b * 256) * 512 + n) * 32 + lane;

    for (int t = 0; t < 256; t++) {
        if (t + 7 < 256) {
            const float* src = gA + (size_t)(t + 7) * tstride;
            uint32_t d = (uint32_t)__cvta_generic_to_shared(&gbuf[wr][(t + 7) & 7][lane]);
            cp4(d,       src + lane);
            cp4(d + 128, src + lane + 32);
            cp4(d + 256, src + lane + 64);
            cp4(d + 384, src + lane + 96);
            cp4(d + 512, src + lane + 128);
            cp4(d + 640, src + lane + 160);
        }
        asm volatile("cp.async.commit_group;" ::: "memory");
        asm volatile("cp.async.wait_group 7;" ::: "memory");

        int s = t & 7;
        float qA0 = gbuf[wr][s][lane];
        float qA1 = gbuf[wr][s][lane + 32];
        float qA2 = gbuf[wr][s][lane + 64];
        float qB0 = gbuf[wr][s][lane + 96];
        float qB1 = gbuf[wr][s][lane + 128];
        float qB2 = gbuf[wr][s][lane + 160];

        float a0A = bh0, a1A = bh1, a2A = bh2;
        float a0B = bh0, a1B = bh1, a2B = bh2;
        float e0A = 0.f, e1A = 0.f, e2A = 0.f;
        float e0B = 0.f, e1B = 0.f, e2B = 0.f;
        #pragma unroll
        for (int jj = 0; jj < 16; jj++) {
            float2 hj = unpack2(__shfl_sync(0xffffffffu, hp, jj));
            float2 hk = unpack2(__shfl_sync(0xffffffffu, hp, jj + 16));
            a0A = fmaf(hj.x, w0[jj], a0A);       a0B = fmaf(hj.y, w0[jj], a0B);
            e0A = fmaf(hk.x, w0[jj + 16], e0A);  e0B = fmaf(hk.y, w0[jj + 16], e0B);
            a1A = fmaf(hj.x, w1[jj], a1A);       a1B = fmaf(hj.y, w1[jj], a1B);
            e1A = fmaf(hk.x, w1[jj + 16], e1A);  e1B = fmaf(hk.y, w1[jj + 16], e1B);
            a2A = fmaf(hj.x, w2[jj], a2A);       a2B = fmaf(hj.y, w2[jj], a2B);
            e2A = fmaf(hk.x, w2[jj + 16], e2A);  e2B = fmaf(hk.y, w2[jj + 16], e2B);
        }
        a0A += e0A; a1A += e1A; a2A += e2A;
        a0B += e0B; a1B += e1B; a2B += e2B;

        float rgA = sigmoid_f(qA0 + a0A);
        float zgA = sigmoid_f(qA1 + a1A);
        float ngA = tanh_f(fmaf(rgA, a2A, qA2));
        hA = fmaf(zgA, hA - ngA, ngA);

        float rgB = sigmoid_f(qB0 + a0B);
        float zgB = sigmoid_f(qB1 + a1B);
        float ngB = tanh_f(fmaf(rgB, a2B, qB2));
        hB = fmaf(zgB, hB - ngB, ngB);

        outp[0]  = hA;
        outp[32] = hB;
        outp += (size_t)512 * 32;

        hp = pack2(hA, hB);
    }
}

// ---------------------------------------------------------------------------
extern "C" void kernel_launch(void* const* d_in, const int* in_sizes, int n_in,
                              void* d_out, int out_size)
{
    (void)in_sizes; (void)n_in; (void)out_size;
    const float* x    = (const float*)d_in[0];
    const float* adj  = (const float*)d_in[1];
    const float* W1   = (const float*)d_in[2];
    const float* b1   = (const float*)d_in[3];
    const float* g1   = (const float*)d_in[4];
    const float* be1  = (const float*)d_in[5];
    const float* W2   = (const float*)d_in[6];
    const float* b2   = (const float*)d_in[7];
    const float* g2   = (const float*)d_in[8];
    const float* be2  = (const float*)d_in[9];
    const float* w_ih = (const float*)d_in[10];
    const float* w_hh = (const float*)d_in[11];
    const float* b_ih = (const float*)d_in[12];
    const float* b_hh = (const float*)d_in[13];
    float* out = (float*)d_out;

    uint32_t *spb;
    float *th, *gv;
    __nv_bfloat16 *ah, *al;
    cudaGetSymbolAddress((void**)&spb, g_spb);
    cudaGetSymbolAddress((void**)&th, g_tanh);
    cudaGetSymbolAddress((void**)&gv, g_gi);
    cudaGetSymbolAddress((void**)&ah, g_adjh);
    cudaGetSymbolAddress((void**)&al, g_adjl);

    static int smem_set = 0;
    if (!smem_set) {
        cudaFuncSetAttribute(k3_mma, cudaFuncAttributeMaxDynamicSharedMemorySize,
                             K3_SMEM_FLOATS * (int)sizeof(float));
        smem_set = 1;
    }

    k0_split<<<(Nn * Nn) / 256, 256>>>(adj, ah, al);
    k1_mma<<<RTOT / 256, 256>>>(x, W1, b1, g1, be1, W2, b2, spb);
    k2_mma<<<dim3(4, BS / 4), 256>>>(ah, al, spb, th);
    k3_mma<<<RTOT / 256, 256, K3_SMEM_FLOATS * sizeof(float)>>>(th, g2, be2, w_ih, b_ih, gv);
    k4_gru<<<BN / 8, 128>>>(gv, w_hh, b_hh, out);
}

// round 15
// speedup vs baseline: 1.1018x; 1.1018x over previous
#include <cuda_runtime.h>
#include <cuda_bf16.h>
#include <math.h>
#include <stdint.h>

#define Bb   8
#define Ss   256
#define Nn   512
#define Ii   32
#define HH   64
#define Oo   32
#define BS   (Bb*Ss)                 // 2048
#define RTOT (BS*Nn)                 // 1,048,576 rows
#define BN   (Bb*Nn)                 // 4096 GRU sequences

typedef unsigned long long ull;

// Scratch
__device__ uint32_t g_spb [(size_t)RTOT * Oo];  // 134 MB: packed (bf16 hi, bf16 lo)
__device__ float    g_tanh[(size_t)RTOT * Oo];
__device__ float    g_gi  [(size_t)RTOT * 96];  // [(b*256+s)*512+n][96]
__device__ __nv_bfloat16 g_adjh[Nn * Nn];
__device__ __nv_bfloat16 g_adjl[Nn * Nn];

__device__ __forceinline__ float warp_sum(float v) {
    #pragma unroll
    for (int o = 16; o > 0; o >>= 1) v += __shfl_xor_sync(0xffffffffu, v, o);
    return v;
}
__device__ __forceinline__ float sigmoid_f(float x) {
    return __fdividef(1.f, 1.f + __expf(-x));
}
__device__ __forceinline__ float tanh_f(float x) {
    float ax = fabsf(x);
    float e  = __expf(-2.f * ax);
    float t  = (1.f - e) * __fdividef(1.f, 1.f + e);
    return copysignf(t, x);
}
__device__ __forceinline__ float tf32_rna(float v) {
    uint32_t u; asm("cvt.rna.tf32.f32 %0,%1;" : "=r"(u) : "f"(v));
    return __uint_as_float(u);
}
__device__ __forceinline__ uint32_t as_u(float f) { return __float_as_uint(f); }
__device__ __forceinline__ float bf_hi(float v) {
    return __bfloat162float(__float2bfloat16_rn(v));
}
__device__ __forceinline__ uint32_t bfpack(float a, float b) {
    __nv_bfloat162 t = __floats2bfloat162_rn(a, b);
    return *reinterpret_cast<uint32_t*>(&t);
}
__device__ __forceinline__ uint32_t pack_hl(float v) {
    float h = bf_hi(v);
    return bfpack(h, v - h);
}
__device__ __forceinline__ ull pack2(float lo, float hi) {
    ull r; asm("mov.b64 %0,{%1,%2};" : "=l"(r) : "f"(lo), "f"(hi)); return r;
}
__device__ __forceinline__ float2 unpack2(ull v) {
    float2 f; asm("mov.b64 {%0,%1},%2;" : "=f"(f.x), "=f"(f.y) : "l"(v)); return f;
}

struct F4 { float x, y, z, w; };
__device__ __forceinline__ void mma_tf32(F4& d,
    uint32_t a0, uint32_t a1, uint32_t a2, uint32_t a3, uint32_t b0, uint32_t b1)
{
    asm volatile(
        "mma.sync.aligned.m16n8k8.row.col.f32.tf32.tf32.f32 "
        "{%0,%1,%2,%3},{%4,%5,%6,%7},{%8,%9},{%0,%1,%2,%3};"
        : "+f"(d.x), "+f"(d.y), "+f"(d.z), "+f"(d.w)
        : "r"(a0), "r"(a1), "r"(a2), "r"(a3), "r"(b0), "r"(b1));
}
__device__ __forceinline__ void mma_bf16(F4& d,
    uint32_t a0, uint32_t a1, uint32_t a2, uint32_t a3, uint32_t b0, uint32_t b1)
{
    asm volatile(
        "mma.sync.aligned.m16n8k16.row.col.f32.bf16.bf16.f32 "
        "{%0,%1,%2,%3},{%4,%5,%6,%7},{%8,%9},{%0,%1,%2,%3};"
        : "+f"(d.x), "+f"(d.y), "+f"(d.z), "+f"(d.w)
        : "r"(a0), "r"(a1), "r"(a2), "r"(a3), "r"(b0), "r"(b1));
}
__device__ __forceinline__ void cp4(uint32_t dst, const float* src) {
    asm volatile("cp.async.ca.shared.global [%0], [%1], 4;" :: "r"(dst), "l"(src));
}

// ---------------------------------------------------------------------------
// K0: split adj into bf16 hi + bf16 residual
// ---------------------------------------------------------------------------
__global__ __launch_bounds__(256) void k0_split(
    const float* __restrict__ adj,
    __nv_bfloat16* __restrict__ hi, __nv_bfloat16* __restrict__ lo)
{
    int i = blockIdx.x * 256 + threadIdx.x;
    float v = adj[i];
    __nv_bfloat16 h = __float2bfloat16_rn(v);
    hi[i] = h;
    lo[i] = __float2bfloat16_rn(v - __bfloat162float(h));
}

// ---------------------------------------------------------------------------
// K1 (bf16 MMA, 3-pass kept for accuracy at K=32): 2 row-tiles per block.
// Stores sp as packed (bf16 hi, bf16 lo) u32.
// ---------------------------------------------------------------------------
__global__ __launch_bounds__(256) void k1_mma(
    const float* __restrict__ x,  const float* __restrict__ W1,
    const float* __restrict__ b1, const float* __restrict__ g1,
    const float* __restrict__ be1,const float* __restrict__ W2,
    const float* __restrict__ b2, uint32_t* __restrict__ spb)
{
    __shared__ __align__(16) uint32_t W1fh[1536], W1fl[1536];
    __shared__ __align__(16) uint32_t W2fh[3072], W2fl[3072];
    __shared__ float2 b1p[32], g1p[32], be1p[32], b2p[16];

    int tid = threadIdx.x, lane = tid & 31, wid = tid >> 5;
    int r = lane >> 2, c = lane & 3;

    #pragma unroll
    for (int p = 0; p < 4; p++) {
        int i = p * 256 + tid;
        int kp = i >> 6, n = i & 63;
        float wa = W1[(2 * kp) * 64 + n], wb = W1[(2 * kp + 1) * 64 + n];
        float ha = bf_hi(wa), hb = bf_hi(wb);
        int kt = kp >> 3, kpl = kp & 7, half = kpl >> 2, cc = kpl & 3;
        int j = n >> 3, rr = n & 7;
        int idx = (kt * 2 + half) * 384 + (rr * 4 + cc) * 12 + j;
        W1fh[idx] = bfpack(ha, hb);
        W1fl[idx] = bfpack(wa - ha, wb - hb);
    }
    #pragma unroll
    for (int p = 0; p < 4; p++) {
        int i = p * 256 + tid;
        int kp = i >> 5, n = i & 31;
        float wa = W2[(2 * kp) * 32 + n], wb = W2[(2 * kp + 1) * 32 + n];
        float ha = bf_hi(wa), hb = bf_hi(wb);
        int kt = kp >> 3, kpl = kp & 7, half = kpl >> 2, cc = kpl & 3;
        int j = n >> 3, rr = n & 7;
        int idx = (kt * 2 + half) * 384 + (rr * 4 + cc) * 12 + j;
        W2fh[idx] = bfpack(ha, hb);
        W2fl[idx] = bfpack(wa - ha, wb - hb);
    }
    if (tid < 32) {
        b1p[tid]  = ((const float2*)b1)[tid];
        g1p[tid]  = ((const float2*)g1)[tid];
        be1p[tid] = ((const float2*)be1)[tid];
        if (tid < 16) b2p[tid] = ((const float2*)b2)[tid];
    }
    __syncthreads();

    for (int tile = 0; tile < 2; tile++) {
        size_t row0 = (size_t)blockIdx.x * 256 + (size_t)tile * 128;

        const float* xr  = x + (row0 + wid * 16 + r) * 32;
        const float* xr8 = xr + 8 * 32;
        float2 xa0[2], xa1[2], xa2[2], xa3[2];
        uint32_t A1h[2][4], A1l[2][4];
        #pragma unroll
        for (int kt = 0; kt < 2; kt++) {
            xa0[kt] = ((const float2*)xr)[kt * 8 + c];
            xa2[kt] = ((const float2*)xr)[kt * 8 + 4 + c];
            xa1[kt] = ((const float2*)xr8)[kt * 8 + c];
            xa3[kt] = ((const float2*)xr8)[kt * 8 + 4 + c];
            float h;
            h = bf_hi(xa0[kt].x); float h2 = bf_hi(xa0[kt].y);
            A1h[kt][0] = bfpack(h, h2); A1l[kt][0] = bfpack(xa0[kt].x - h, xa0[kt].y - h2);
            h = bf_hi(xa1[kt].x); h2 = bf_hi(xa1[kt].y);
            A1h[kt][1] = bfpack(h, h2); A1l[kt][1] = bfpack(xa1[kt].x - h, xa1[kt].y - h2);
            h = bf_hi(xa2[kt].x); h2 = bf_hi(xa2[kt].y);
            A1h[kt][2] = bfpack(h, h2); A1l[kt][2] = bfpack(xa2[kt].x - h, xa2[kt].y - h2);
            h = bf_hi(xa3[kt].x); h2 = bf_hi(xa3[kt].y);
            A1h[kt][3] = bfpack(h, h2); A1l[kt][3] = bfpack(xa3[kt].x - h, xa3[kt].y - h2);
        }

        F4 acc1[8];
        #pragma unroll
        for (int j = 0; j < 8; j++) { acc1[j].x = acc1[j].y = acc1[j].z = acc1[j].w = 0.f; }
        #pragma unroll
        for (int kt = 0; kt < 2; kt++) {
            uint32_t bh0[8], bh1[8], bl0[8], bl1[8];
            {
                const uint4* p0 = (const uint4*)&W1fh[(kt * 2 + 0) * 384 + lane * 12];
                const uint4* p1 = (const uint4*)&W1fh[(kt * 2 + 1) * 384 + lane * 12];
                const uint4* q0 = (const uint4*)&W1fl[(kt * 2 + 0) * 384 + lane * 12];
                const uint4* q1 = (const uint4*)&W1fl[(kt * 2 + 1) * 384 + lane * 12];
                uint4 t;
                t = p0[0]; bh0[0]=t.x; bh0[1]=t.y; bh0[2]=t.z; bh0[3]=t.w;
                t = p0[1]; bh0[4]=t.x; bh0[5]=t.y; bh0[6]=t.z; bh0[7]=t.w;
                t = p1[0]; bh1[0]=t.x; bh1[1]=t.y; bh1[2]=t.z; bh1[3]=t.w;
                t = p1[1]; bh1[4]=t.x; bh1[5]=t.y; bh1[6]=t.z; bh1[7]=t.w;
                t = q0[0]; bl0[0]=t.x; bl0[1]=t.y; bl0[2]=t.z; bl0[3]=t.w;
                t = q0[1]; bl0[4]=t.x; bl0[5]=t.y; bl0[6]=t.z; bl0[7]=t.w;
                t = q1[0]; bl1[0]=t.x; bl1[1]=t.y; bl1[2]=t.z; bl1[3]=t.w;
                t = q1[1]; bl1[4]=t.x; bl1[5]=t.y; bl1[6]=t.z; bl1[7]=t.w;
            }
            #pragma unroll
            for (int j = 0; j < 8; j++) {
                mma_bf16(acc1[j], A1h[kt][0], A1h[kt][1], A1h[kt][2], A1h[kt][3], bh0[j], bh1[j]);
                mma_bf16(acc1[j], A1l[kt][0], A1l[kt][1], A1l[kt][2], A1l[kt][3], bh0[j], bh1[j]);
                mma_bf16(acc1[j], A1h[kt][0], A1h[kt][1], A1h[kt][2], A1h[kt][3], bl0[j], bl1[j]);
            }
        }

        float s0 = 0.f, q0s = 0.f, s1 = 0.f, q1s = 0.f;
        #pragma unroll
        for (int j = 0; j < 8; j++) {
            float2 b = b1p[c + 4 * j];
            acc1[j].x += b.x; acc1[j].y += b.y; acc1[j].z += b.x; acc1[j].w += b.y;
            s0 += acc1[j].x + acc1[j].y;
            q0s += acc1[j].x * acc1[j].x + acc1[j].y * acc1[j].y;
            s1 += acc1[j].z + acc1[j].w;
            q1s += acc1[j].z * acc1[j].z + acc1[j].w * acc1[j].w;
        }
        s0 += __shfl_xor_sync(0xffffffffu, s0, 1); s0 += __shfl_xor_sync(0xffffffffu, s0, 2);
        q0s += __shfl_xor_sync(0xffffffffu, q0s, 1); q0s += __shfl_xor_sync(0xffffffffu, q0s, 2);
        s1 += __shfl_xor_sync(0xffffffffu, s1, 1); s1 += __shfl_xor_sync(0xffffffffu, s1, 2);
        q1s += __shfl_xor_sync(0xffffffffu, q1s, 1); q1s += __shfl_xor_sync(0xffffffffu, q1s, 2);
        float mu0 = s0 * (1.f / 64.f), mu1 = s1 * (1.f / 64.f);
        float rstd0 = rsqrtf(fmaf(-mu0, mu0, q0s * (1.f / 64.f)) + 1e-5f);
        float rstd1 = rsqrtf(fmaf(-mu1, mu1, q1s * (1.f / 64.f)) + 1e-5f);
        #pragma unroll
        for (int j = 0; j < 8; j++) {
            float2 g = g1p[c + 4 * j], be = be1p[c + 4 * j];
            acc1[j].x = fmaxf(fmaf((acc1[j].x - mu0) * rstd0, g.x, be.x), 0.f);
            acc1[j].y = fmaxf(fmaf((acc1[j].y - mu0) * rstd0, g.y, be.y), 0.f);
            acc1[j].z = fmaxf(fmaf((acc1[j].z - mu1) * rstd1, g.x, be.x), 0.f);
            acc1[j].w = fmaxf(fmaf((acc1[j].w - mu1) * rstd1, g.y, be.y), 0.f);
        }

        uint32_t A2h[4][4], A2l[4][4];
        #pragma unroll
        for (int kt = 0; kt < 4; kt++) {
            F4 e = acc1[2 * kt], o = acc1[2 * kt + 1];
            float h;
            h = bf_hi(e.x); float h2 = bf_hi(e.y);
            A2h[kt][0] = bfpack(h, h2); A2l[kt][0] = bfpack(e.x - h, e.y - h2);
            h = bf_hi(e.z); h2 = bf_hi(e.w);
            A2h[kt][1] = bfpack(h, h2); A2l[kt][1] = bfpack(e.z - h, e.w - h2);
            h = bf_hi(o.x); h2 = bf_hi(o.y);
            A2h[kt][2] = bfpack(h, h2); A2l[kt][2] = bfpack(o.x - h, o.y - h2);
            h = bf_hi(o.z); h2 = bf_hi(o.w);
            A2h[kt][3] = bfpack(h, h2); A2l[kt][3] = bfpack(o.z - h, o.w - h2);
        }

        F4 acc2[4];
        #pragma unroll
        for (int j = 0; j < 4; j++) { acc2[j].x = acc2[j].y = acc2[j].z = acc2[j].w = 0.f; }
        #pragma unroll
        for (int kt = 0; kt < 4; kt++) {
            uint4 h0 = *(const uint4*)&W2fh[(kt * 2 + 0) * 384 + lane * 12];
            uint4 h1 = *(const uint4*)&W2fh[(kt * 2 + 1) * 384 + lane * 12];
            uint4 l0 = *(const uint4*)&W2fl[(kt * 2 + 0) * 384 + lane * 12];
            uint4 l1 = *(const uint4*)&W2fl[(kt * 2 + 1) * 384 + lane * 12];
            uint32_t bh0[4] = {h0.x, h0.y, h0.z, h0.w};
            uint32_t bh1[4] = {h1.x, h1.y, h1.z, h1.w};
            uint32_t bl0[4] = {l0.x, l0.y, l0.z, l0.w};
            uint32_t bl1[4] = {l1.x, l1.y, l1.z, l1.w};
            #pragma unroll
            for (int j = 0; j < 4; j++) {
                mma_bf16(acc2[j], A2h[kt][0], A2h[kt][1], A2h[kt][2], A2h[kt][3], bh0[j], bh1[j]);
                mma_bf16(acc2[j], A2l[kt][0], A2l[kt][1], A2l[kt][2], A2l[kt][3], bh0[j], bh1[j]);
                mma_bf16(acc2[j], A2h[kt][0], A2h[kt][1], A2h[kt][2], A2h[kt][3], bl0[j], bl1[j]);
            }
        }

        size_t orow = row0 + wid * 16 + r;
        #pragma unroll
        for (int j = 0; j < 4; j++) {
            float2 b = b2p[4 * j + c];
            int kth = j >> 1;
            float2 rx0 = (j & 1) ? xa2[kth] : xa0[kth];
            float2 rx1 = (j & 1) ? xa3[kth] : xa1[kth];
            float v00 = acc2[j].x + b.x + rx0.x, v01 = acc2[j].y + b.y + rx0.y;
            float v10 = acc2[j].z + b.x + rx1.x, v11 = acc2[j].w + b.y + rx1.y;
            uint2 s0v = { pack_hl(v00), pack_hl(v01) };
            uint2 s1v = { pack_hl(v10), pack_hl(v11) };
            *(uint2*)&spb[orow * 32 + 8 * j + 2 * c]       = s0v;
            *(uint2*)&spb[(orow + 8) * 32 + 8 * j + 2 * c] = s1v;
        }
    }
}

// ---------------------------------------------------------------------------
// K2 (bf16 m16n8k16, NOW 2-PASS: Ah*Bh + Al*Bh; Ah*Bl dropped — K=512
// averaging keeps the error ~1e-5). B lo staging removed entirely.
// ---------------------------------------------------------------------------
__global__ __launch_bounds__(256) void k2_mma(
    const __nv_bfloat16* __restrict__ adjh, const __nv_bfloat16* __restrict__ adjl,
    const uint32_t* __restrict__ spb, float* __restrict__ out)
{
    __shared__ __align__(16) uint32_t Ahs[2048], Als[2048];
    __shared__ __align__(16) uint32_t Bhs[2560];

    int tid = threadIdx.x, lane = tid & 31, wid = tid >> 5;
    int n0  = blockIdx.x * 128;
    int bs0 = blockIdx.y * 4;
    int r = lane >> 2, c = lane & 3;

    F4 acc[4][4];
    #pragma unroll
    for (int u = 0; u < 4; u++)
        #pragma unroll
        for (int j = 0; j < 4; j++) { acc[u][j].x = acc[u][j].y = acc[u][j].z = acc[u][j].w = 0.f; }

    for (int mc = 0; mc < 512; mc += 32) {
        __syncthreads();
        #pragma unroll
        for (int p = 0; p < 2; p++) {
            int i = p * 256 + tid;
            int n = i >> 2, seg = i & 3;
            size_t boff = ((size_t)(n0 + n) * 512 + mc) * 2 + seg * 16;
            uint4 vh = *(const uint4*)((const char*)adjh + boff);
            uint4 vl = *(const uint4*)((const char*)adjl + boff);
            int w = n >> 4, rr = n & 15, rf = rr & 7, rh = rr >> 3, kt = seg >> 1;
            int base = (w * 2 + kt) * 128 + rf * 16;
            uint32_t ah[4] = {vh.x, vh.y, vh.z, vh.w};
            uint32_t al[4] = {vl.x, vl.y, vl.z, vl.w};
            #pragma unroll
            for (int u = 0; u < 4; u++) {
                int kpl = (seg & 1) * 4 + u;
                int cc = kpl & 3, side = kpl >> 2;
                Ahs[base + cc * 4 + side * 2 + rh] = ah[u];
                Als[base + cc * 4 + side * 2 + rh] = al[u];
            }
        }
        #pragma unroll
        for (int p = 0; p < 2; p++) {
            int u = p * 2 + (tid >> 7);
            int rem = tid & 127;
            int kp = rem >> 3, q = rem & 7, col0 = q * 4;
            const uint32_t* s0 = &spb[((size_t)(bs0 + u) * 512 + mc + 2 * kp) * 32 + col0];
            uint4 A  = *(const uint4*)s0;
            uint4 Bv = *(const uint4*)(s0 + 32);
            int kt = kp >> 3, kpl = kp & 7, half = kpl >> 2, cc = kpl & 3;
            int bb = ((u * 2 + kt) * 2 + half) * 160 + cc * 40;
            uint32_t av[4] = {A.x, A.y, A.z, A.w};
            uint32_t bv[4] = {Bv.x, Bv.y, Bv.z, Bv.w};
            #pragma unroll
            for (int i = 0; i < 4; i++) {
                int col = col0 + i, j = col >> 3, rr = col & 7;
                Bhs[bb + rr * 4 + j] = __byte_perm(av[i], bv[i], 0x5410);
            }
        }
        __syncthreads();

        #pragma unroll
        for (int kt = 0; kt < 2; kt++) {
            uint4 Ah4 = *(const uint4*)&Ahs[(wid * 2 + kt) * 128 + lane * 4];
            uint4 Al4 = *(const uint4*)&Als[(wid * 2 + kt) * 128 + lane * 4];
            #pragma unroll
            for (int u = 0; u < 4; u++) {
                int bb = ((u * 2 + kt) * 2) * 160 + c * 40 + r * 4;
                uint4 h0 = *(const uint4*)&Bhs[bb];
                uint4 h1 = *(const uint4*)&Bhs[bb + 160];
                uint32_t bh0[4] = {h0.x, h0.y, h0.z, h0.w};
                uint32_t bh1[4] = {h1.x, h1.y, h1.z, h1.w};
                #pragma unroll
                for (int j = 0; j < 4; j++) {
                    mma_bf16(acc[u][j], Ah4.x, Ah4.y, Ah4.z, Ah4.w, bh0[j], bh1[j]);
                    mma_bf16(acc[u][j], Al4.x, Al4.y, Al4.z, Al4.w, bh0[j], bh1[j]);
                }
            }
        }
    }

    int c2 = c * 2;
    #pragma unroll
    for (int u = 0; u < 4; u++) {
        size_t bsrow = (size_t)(bs0 + u) * 512;
        #pragma unroll
        for (int j = 0; j < 4; j++) {
            int col  = j * 8 + c2;
            int row0 = n0 + wid * 16 + r;
            float2 v0 = { tanh_f(acc[u][j].x), tanh_f(acc[u][j].y) };
            float2 v1 = { tanh_f(acc[u][j].z), tanh_f(acc[u][j].w) };
            *(float2*)&out[(bsrow + row0)     * 32 + col] = v0;
            *(float2*)&out[(bsrow + row0 + 8) * 32 + col] = v1;
        }
    }
}

// ---------------------------------------------------------------------------
// K3 (tf32 3-pass): B fragment-pair prestage + 2 row-tiles/block.
// ---------------------------------------------------------------------------
#define K3_SMEM_FLOATS (2*4608 + 2*3168 + 96)

__global__ __launch_bounds__(256) void k3_mma(
    const float* __restrict__ tin, const float* __restrict__ g2,
    const float* __restrict__ be2, const float* __restrict__ w_ih,
    const float* __restrict__ b_ih, float* __restrict__ gi)
{
    extern __shared__ float smem[];
    float* Ah  = smem;
    float* Al  = Ah + 4608;
    float* Bfh = Al + 4608;
    float* Bfl = Bfh + 3168;
    float* bis = Bfl + 3168;

    int tid = threadIdx.x, lane = tid & 31, wid = tid >> 5;
    int r = lane >> 2, c = lane & 3;
    int mbase = wid * 16;

    #pragma unroll
    for (int p = 0; p < 12; p++) {
        int v = p * 256 + tid;
        int k = v & 31, col = v >> 5;
        float w = w_ih[col * 32 + k];
        float h = tf32_rna(w);
        int kt = k >> 3, cc = k & 3, reg = (k >> 2) & 1;
        int j = col >> 3, rr = col & 7;
        int addr = kt * 792 + j * 66 + (rr * 4 + cc) * 2 + reg;
        Bfh[addr] = h;
        Bfl[addr] = w - h;
    }
    if (tid < 96) bis[tid] = b_ih[tid];

    float g2v = g2[lane], be2v = be2[lane];

    for (int tile = 0; tile < 2; tile++) {
        size_t rr0 = (size_t)blockIdx.x * 256 + (size_t)tile * 128;
        if (tile) __syncthreads();

        #pragma unroll
        for (int q = 0; q < 16; q++) {
            int row = wid * 16 + q;
            float v = tin[(rr0 + row) * 32 + lane];
            float mu = warp_sum(v) * (1.f / 32.f);
            float d = v - mu;
            float var = warp_sum(d * d) * (1.f / 32.f);
            float ln = fmaf(d * rsqrtf(var + 1e-5f), g2v, be2v);
            float lh = tf32_rna(ln);
            Ah[row * 36 + lane] = lh;
            Al[row * 36 + lane] = ln - lh;
        }
        __syncthreads();

        F4 acc[12];
        #pragma unroll
        for (int j = 0; j < 12; j++) { acc[j].x = acc[j].y = acc[j].z = acc[j].w = 0.f; }

        #pragma unroll
        for (int kt = 0; kt < 4; kt++) {
            int kb = kt * 8;
            uint32_t ah0 = as_u(Ah[(mbase + r)     * 36 + kb + c]);
            uint32_t ah1 = as_u(Ah[(mbase + 8 + r) * 36 + kb + c]);
            uint32_t ah2 = as_u(Ah[(mbase + r)     * 36 + kb + 4 + c]);
            uint32_t ah3 = as_u(Ah[(mbase + 8 + r) * 36 + kb + 4 + c]);
            uint32_t al0 = as_u(Al[(mbase + r)     * 36 + kb + c]);
            uint32_t al1 = as_u(Al[(mbase + 8 + r) * 36 + kb + c]);
            uint32_t al2 = as_u(Al[(mbase + r)     * 36 + kb + 4 + c]);
            uint32_t al3 = as_u(Al[(mbase + 8 + r) * 36 + kb + 4 + c]);
            const float* bhp = &Bfh[kt * 792 + lane * 2];
            const float* blp = &Bfl[kt * 792 + lane * 2];
            #pragma unroll
            for (int j = 0; j < 12; j++) {
                float2 bh = *(const float2*)(bhp + j * 66);
                float2 bl = *(const float2*)(blp + j * 66);
                mma_tf32(acc[j], ah0, ah1, ah2, ah3, as_u(bh.x), as_u(bh.y));
                mma_tf32(acc[j], al0, al1, al2, al3, as_u(bh.x), as_u(bh.y));
                mma_tf32(acc[j], ah0, ah1, ah2, ah3, as_u(bl.x), as_u(bl.y));
            }
        }

        int c2 = c * 2;
        #pragma unroll
        for (int j = 0; j < 12; j++) {
            int col = j * 8 + c2;
            float2 bi = *(const float2*)&bis[col];
            size_t row0 = rr0 + mbase + r;
            float2 v0 = { acc[j].x + bi.x, acc[j].y + bi.y };
            float2 v1 = { acc[j].z + bi.x, acc[j].w + bi.y };
            *(float2*)&gi[row0 * 96 + col]       = v0;
            *(float2*)&gi[(row0 + 8) * 96 + col] = v1;
        }
    }
}

// ---------------------------------------------------------------------------
// K4 (R11 version): 2 sequences per warp, single wave.
// ---------------------------------------------------------------------------
__global__ __launch_bounds__(128, 4) void k4_gru(
    const float* __restrict__ gi, const float* __restrict__ w_hh,
    const float* __restrict__ b_hh, float* __restrict__ out)
{
    __shared__ float gbuf[4][8][192];

    int tid = threadIdx.x, lane = tid & 31, wr = tid >> 5;
    int p = blockIdx.x * 4 + wr;
    int bn = 2 * p;
    int b = bn >> 9, n = bn & 511;

    float w0[32], w1[32], w2[32];
    #pragma unroll
    for (int m = 0; m < 8; m++) {
        float4 a = ((const float4*)(w_hh + (size_t)lane * 32))[m];
        float4 cc = ((const float4*)(w_hh + (size_t)(lane + 32) * 32))[m];
        float4 d = ((const float4*)(w_hh + (size_t)(lane + 64) * 32))[m];
        w0[4*m+0]=a.x;  w0[4*m+1]=a.y;  w0[4*m+2]=a.z;  w0[4*m+3]=a.w;
        w1[4*m+0]=cc.x; w1[4*m+1]=cc.y; w1[4*m+2]=cc.z; w1[4*m+3]=cc.w;
        w2[4*m+0]=d.x;  w2[4*m+1]=d.y;  w2[4*m+2]=d.z;  w2[4*m+3]=d.w;
    }
    float bh0 = b_hh[lane], bh1 = b_hh[lane + 32], bh2 = b_hh[lane + 64];

    const size_t tstride = (size_t)512 * 96;
    const float* gA = gi + ((size_t)(b * 256) * 512 + n) * 96;

    #pragma unroll
    for (int s = 0; s < 7; s++) {
        const float* src = gA + (size_t)s * tstride;
        uint32_t d = (uint32_t)__cvta_generic_to_shared(&gbuf[wr][s][lane]);
        cp4(d,       src + lane);
        cp4(d + 128, src + lane + 32);
        cp4(d + 256, src + lane + 64);
        cp4(d + 384, src + lane + 96);
        cp4(d + 512, src + lane + 128);
        cp4(d + 640, src + lane + 160);
        asm volatile("cp.async.commit_group;" ::: "memory");
    }

    float hA = 0.f, hB = 0.f;
    ull hp = 0;
    float* outp = out + ((size_t)(b * 256) * 512 + n) * 32 + lane;

    for (int t = 0; t < 256; t++) {
        if (t + 7 < 256) {
            const float* src = gA + (size_t)(t + 7) * tstride;
            uint32_t d = (uint32_t)__cvta_generic_to_shared(&gbuf[wr][(t + 7) & 7][lane]);
            cp4(d,       src + lane);
            cp4(d + 128, src + lane + 32);
            cp4(d + 256, src + lane + 64);
            cp4(d + 384, src + lane + 96);
            cp4(d + 512, src + lane + 128);
            cp4(d + 640, src + lane + 160);
        }
        asm volatile("cp.async.commit_group;" ::: "memory");
        asm volatile("cp.async.wait_group 7;" ::: "memory");

        int s = t & 7;
        float qA0 = gbuf[wr][s][lane];
        float qA1 = gbuf[wr][s][lane + 32];
        float qA2 = gbuf[wr][s][lane + 64];
        float qB0 = gbuf[wr][s][lane + 96];
        float qB1 = gbuf[wr][s][lane + 128];
        float qB2 = gbuf[wr][s][lane + 160];

        float a0A = bh0, a1A = bh1, a2A = bh2;
        float a0B = bh0, a1B = bh1, a2B = bh2;
        float e0A = 0.f, e1A = 0.f, e2A = 0.f;
        float e0B = 0.f, e1B = 0.f, e2B = 0.f;
        #pragma unroll
        for (int jj = 0; jj < 16; jj++) {
            float2 hj = unpack2(__shfl_sync(0xffffffffu, hp, jj));
            float2 hk = unpack2(__shfl_sync(0xffffffffu, hp, jj + 16));
            a0A = fmaf(hj.x, w0[jj], a0A);       a0B = fmaf(hj.y, w0[jj], a0B);
            e0A = fmaf(hk.x, w0[jj + 16], e0A);  e0B = fmaf(hk.y, w0[jj + 16], e0B);
            a1A = fmaf(hj.x, w1[jj], a1A);       a1B = fmaf(hj.y, w1[jj], a1B);
            e1A = fmaf(hk.x, w1[jj + 16], e1A);  e1B = fmaf(hk.y, w1[jj + 16], e1B);
            a2A = fmaf(hj.x, w2[jj], a2A);       a2B = fmaf(hj.y, w2[jj], a2B);
            e2A = fmaf(hk.x, w2[jj + 16], e2A);  e2B = fmaf(hk.y, w2[jj + 16], e2B);
        }
        a0A += e0A; a1A += e1A; a2A += e2A;
        a0B += e0B; a1B += e1B; a2B += e2B;

        float rgA = sigmoid_f(qA0 + a0A);
        float zgA = sigmoid_f(qA1 + a1A);
        float ngA = tanh_f(fmaf(rgA, a2A, qA2));
        hA = fmaf(zgA, hA - ngA, ngA);

        float rgB = sigmoid_f(qB0 + a0B);
        float zgB = sigmoid_f(qB1 + a1B);
        float ngB = tanh_f(fmaf(rgB, a2B, qB2));
        hB = fmaf(zgB, hB - ngB, ngB);

        outp[0]  = hA;
        outp[32] = hB;
        outp += (size_t)512 * 32;

        hp = pack2(hA, hB);
    }
}

// ---------------------------------------------------------------------------
extern "C" void kernel_launch(void* const* d_in, const int* in_sizes, int n_in,
                              void* d_out, int out_size)
{
    (void)in_sizes; (void)n_in; (void)out_size;
    const float* x    = (const float*)d_in[0];
    const float* adj  = (const float*)d_in[1];
    const float* W1   = (const float*)d_in[2];
    const float* b1   = (const float*)d_in[3];
    const float* g1   = (const float*)d_in[4];
    const float* be1  = (const float*)d_in[5];
    const float* W2   = (const float*)d_in[6];
    const float* b2   = (const float*)d_in[7];
    const float* g2   = (const float*)d_in[8];
    const float* be2  = (const float*)d_in[9];
    const float* w_ih = (const float*)d_in[10];
    const float* w_hh = (const float*)d_in[11];
    const float* b_ih = (const float*)d_in[12];
    const float* b_hh = (const float*)d_in[13];
    float* out = (float*)d_out;

    uint32_t *spb;
    float *th, *gv;
    __nv_bfloat16 *ah, *al;
    cudaGetSymbolAddress((void**)&spb, g_spb);
    cudaGetSymbolAddress((void**)&th, g_tanh);
    cudaGetSymbolAddress((void**)&gv, g_gi);
    cudaGetSymbolAddress((void**)&ah, g_adjh);
    cudaGetSymbolAddress((void**)&al, g_adjl);

    static int smem_set = 0;
    if (!smem_set) {
        cudaFuncSetAttribute(k3_mma, cudaFuncAttributeMaxDynamicSharedMemorySize,
                             K3_SMEM_FLOATS * (int)sizeof(float));
        smem_set = 1;
    }

    k0_split<<<(Nn * Nn) / 256, 256>>>(adj, ah, al);
    k1_mma<<<RTOT / 256, 256>>>(x, W1, b1, g1, be1, W2, b2, spb);
    k2_mma<<<dim3(4, BS / 4), 256>>>(ah, al, spb, th);
    k3_mma<<<RTOT / 256, 256, K3_SMEM_FLOATS * sizeof(float)>>>(th, g2, be2, w_ih, b_ih, gv);
    k4_gru<<<BN / 8, 128>>>(gv, w_hh, b_hh, out);
}

// round 16
// speedup vs baseline: 1.2932x; 1.1737x over previous
#include <cuda_runtime.h>
#include <cuda_bf16.h>
#include <cuda_fp16.h>
#include <math.h>
#include <stdint.h>

#define Bb   8
#define Ss   256
#define Nn   512
#define Ii   32
#define HH   64
#define Oo   32
#define BS   (Bb*Ss)                 // 2048
#define RTOT (BS*Nn)                 // 1,048,576 rows
#define BN   (Bb*Nn)                 // 4096 GRU sequences

typedef unsigned long long ull;

// Scratch
__device__ __half g_sph [(size_t)RTOT * Oo];    // 67 MB: sp in fp16
__device__ float  g_tanh[(size_t)RTOT * Oo];
__device__ float  g_gi  [(size_t)RTOT * 96];    // [(b*256+s)*512+n][96]
__device__ __half g_adjf[Nn * Nn];              // adj in fp16

__device__ __forceinline__ float warp_sum(float v) {
    #pragma unroll
    for (int o = 16; o > 0; o >>= 1) v += __shfl_xor_sync(0xffffffffu, v, o);
    return v;
}
__device__ __forceinline__ float sigmoid_f(float x) {
    return __fdividef(1.f, 1.f + __expf(-x));
}
__device__ __forceinline__ float tanh_f(float x) {
    float ax = fabsf(x);
    float e  = __expf(-2.f * ax);
    float t  = (1.f - e) * __fdividef(1.f, 1.f + e);
    return copysignf(t, x);
}
__device__ __forceinline__ float tf32_rna(float v) {
    uint32_t u; asm("cvt.rna.tf32.f32 %0,%1;" : "=r"(u) : "f"(v));
    return __uint_as_float(u);
}
__device__ __forceinline__ uint32_t as_u(float f) { return __float_as_uint(f); }
__device__ __forceinline__ float bf_hi(float v) {
    return __bfloat162float(__float2bfloat16_rn(v));
}
__device__ __forceinline__ uint32_t bfpack(float a, float b) {
    __nv_bfloat162 t = __floats2bfloat162_rn(a, b);
    return *reinterpret_cast<uint32_t*>(&t);
}
__device__ __forceinline__ uint32_t h2pack(float a, float b) {
    __half2 t = __floats2half2_rn(a, b);
    return *reinterpret_cast<uint32_t*>(&t);
}
__device__ __forceinline__ ull pack2(float lo, float hi) {
    ull r; asm("mov.b64 %0,{%1,%2};" : "=l"(r) : "f"(lo), "f"(hi)); return r;
}
__device__ __forceinline__ float2 unpack2(ull v) {
    float2 f; asm("mov.b64 {%0,%1},%2;" : "=f"(f.x), "=f"(f.y) : "l"(v)); return f;
}

struct F4 { float x, y, z, w; };
__device__ __forceinline__ void mma_tf32(F4& d,
    uint32_t a0, uint32_t a1, uint32_t a2, uint32_t a3, uint32_t b0, uint32_t b1)
{
    asm volatile(
        "mma.sync.aligned.m16n8k8.row.col.f32.tf32.tf32.f32 "
        "{%0,%1,%2,%3},{%4,%5,%6,%7},{%8,%9},{%0,%1,%2,%3};"
        : "+f"(d.x), "+f"(d.y), "+f"(d.z), "+f"(d.w)
        : "r"(a0), "r"(a1), "r"(a2), "r"(a3), "r"(b0), "r"(b1));
}
__device__ __forceinline__ void mma_bf16(F4& d,
    uint32_t a0, uint32_t a1, uint32_t a2, uint32_t a3, uint32_t b0, uint32_t b1)
{
    asm volatile(
        "mma.sync.aligned.m16n8k16.row.col.f32.bf16.bf16.f32 "
        "{%0,%1,%2,%3},{%4,%5,%6,%7},{%8,%9},{%0,%1,%2,%3};"
        : "+f"(d.x), "+f"(d.y), "+f"(d.z), "+f"(d.w)
        : "r"(a0), "r"(a1), "r"(a2), "r"(a3), "r"(b0), "r"(b1));
}
__device__ __forceinline__ void mma_f16(F4& d,
    uint32_t a0, uint32_t a1, uint32_t a2, uint32_t a3, uint32_t b0, uint32_t b1)
{
    asm volatile(
        "mma.sync.aligned.m16n8k16.row.col.f32.f16.f16.f32 "
        "{%0,%1,%2,%3},{%4,%5,%6,%7},{%8,%9},{%0,%1,%2,%3};"
        : "+f"(d.x), "+f"(d.y), "+f"(d.z), "+f"(d.w)
        : "r"(a0), "r"(a1), "r"(a2), "r"(a3), "r"(b0), "r"(b1));
}
__device__ __forceinline__ void cp4(uint32_t dst, const float* src) {
    asm volatile("cp.async.ca.shared.global [%0], [%1], 4;" :: "r"(dst), "l"(src));
}

// ---------------------------------------------------------------------------
// K0: adj -> fp16
// ---------------------------------------------------------------------------
__global__ __launch_bounds__(256) void k0_split(
    const float* __restrict__ adj, __half* __restrict__ af)
{
    int i = blockIdx.x * 256 + threadIdx.x;
    af[i] = __float2half_rn(adj[i]);
}

// ---------------------------------------------------------------------------
// K1 (bf16 MMA, 3-pass): 2 row-tiles per block; stores sp as fp16.
// ---------------------------------------------------------------------------
__global__ __launch_bounds__(256) void k1_mma(
    const float* __restrict__ x,  const float* __restrict__ W1,
    const float* __restrict__ b1, const float* __restrict__ g1,
    const float* __restrict__ be1,const float* __restrict__ W2,
    const float* __restrict__ b2, __half* __restrict__ sph)
{
    __shared__ __align__(16) uint32_t W1fh[1536], W1fl[1536];
    __shared__ __align__(16) uint32_t W2fh[3072], W2fl[3072];
    __shared__ float2 b1p[32], g1p[32], be1p[32], b2p[16];

    int tid = threadIdx.x, lane = tid & 31, wid = tid >> 5;
    int r = lane >> 2, c = lane & 3;

    #pragma unroll
    for (int p = 0; p < 4; p++) {
        int i = p * 256 + tid;
        int kp = i >> 6, n = i & 63;
        float wa = W1[(2 * kp) * 64 + n], wb = W1[(2 * kp + 1) * 64 + n];
        float ha = bf_hi(wa), hb = bf_hi(wb);
        int kt = kp >> 3, kpl = kp & 7, half = kpl >> 2, cc = kpl & 3;
        int j = n >> 3, rr = n & 7;
        int idx = (kt * 2 + half) * 384 + (rr * 4 + cc) * 12 + j;
        W1fh[idx] = bfpack(ha, hb);
        W1fl[idx] = bfpack(wa - ha, wb - hb);
    }
    #pragma unroll
    for (int p = 0; p < 4; p++) {
        int i = p * 256 + tid;
        int kp = i >> 5, n = i & 31;
        float wa = W2[(2 * kp) * 32 + n], wb = W2[(2 * kp + 1) * 32 + n];
        float ha = bf_hi(wa), hb = bf_hi(wb);
        int kt = kp >> 3, kpl = kp & 7, half = kpl >> 2, cc = kpl & 3;
        int j = n >> 3, rr = n & 7;
        int idx = (kt * 2 + half) * 384 + (rr * 4 + cc) * 12 + j;
        W2fh[idx] = bfpack(ha, hb);
        W2fl[idx] = bfpack(wa - ha, wb - hb);
    }
    if (tid < 32) {
        b1p[tid]  = ((const float2*)b1)[tid];
        g1p[tid]  = ((const float2*)g1)[tid];
        be1p[tid] = ((const float2*)be1)[tid];
        if (tid < 16) b2p[tid] = ((const float2*)b2)[tid];
    }
    __syncthreads();

    for (int tile = 0; tile < 2; tile++) {
        size_t row0 = (size_t)blockIdx.x * 256 + (size_t)tile * 128;

        const float* xr  = x + (row0 + wid * 16 + r) * 32;
        const float* xr8 = xr + 8 * 32;
        float2 xa0[2], xa1[2], xa2[2], xa3[2];
        uint32_t A1h[2][4], A1l[2][4];
        #pragma unroll
        for (int kt = 0; kt < 2; kt++) {
            xa0[kt] = ((const float2*)xr)[kt * 8 + c];
            xa2[kt] = ((const float2*)xr)[kt * 8 + 4 + c];
            xa1[kt] = ((const float2*)xr8)[kt * 8 + c];
            xa3[kt] = ((const float2*)xr8)[kt * 8 + 4 + c];
            float h;
            h = bf_hi(xa0[kt].x); float h2 = bf_hi(xa0[kt].y);
            A1h[kt][0] = bfpack(h, h2); A1l[kt][0] = bfpack(xa0[kt].x - h, xa0[kt].y - h2);
            h = bf_hi(xa1[kt].x); h2 = bf_hi(xa1[kt].y);
            A1h[kt][1] = bfpack(h, h2); A1l[kt][1] = bfpack(xa1[kt].x - h, xa1[kt].y - h2);
            h = bf_hi(xa2[kt].x); h2 = bf_hi(xa2[kt].y);
            A1h[kt][2] = bfpack(h, h2); A1l[kt][2] = bfpack(xa2[kt].x - h, xa2[kt].y - h2);
            h = bf_hi(xa3[kt].x); h2 = bf_hi(xa3[kt].y);
            A1h[kt][3] = bfpack(h, h2); A1l[kt][3] = bfpack(xa3[kt].x - h, xa3[kt].y - h2);
        }

        F4 acc1[8];
        #pragma unroll
        for (int j = 0; j < 8; j++) { acc1[j].x = acc1[j].y = acc1[j].z = acc1[j].w = 0.f; }
        #pragma unroll
        for (int kt = 0; kt < 2; kt++) {
            uint32_t bh0[8], bh1[8], bl0[8], bl1[8];
            {
                const uint4* p0 = (const uint4*)&W1fh[(kt * 2 + 0) * 384 + lane * 12];
                const uint4* p1 = (const uint4*)&W1fh[(kt * 2 + 1) * 384 + lane * 12];
                const uint4* q0 = (const uint4*)&W1fl[(kt * 2 + 0) * 384 + lane * 12];
                const uint4* q1 = (const uint4*)&W1fl[(kt * 2 + 1) * 384 + lane * 12];
                uint4 t;
                t = p0[0]; bh0[0]=t.x; bh0[1]=t.y; bh0[2]=t.z; bh0[3]=t.w;
                t = p0[1]; bh0[4]=t.x; bh0[5]=t.y; bh0[6]=t.z; bh0[7]=t.w;
                t = p1[0]; bh1[0]=t.x; bh1[1]=t.y; bh1[2]=t.z; bh1[3]=t.w;
                t = p1[1]; bh1[4]=t.x; bh1[5]=t.y; bh1[6]=t.z; bh1[7]=t.w;
                t = q0[0]; bl0[0]=t.x; bl0[1]=t.y; bl0[2]=t.z; bl0[3]=t.w;
                t = q0[1]; bl0[4]=t.x; bl0[5]=t.y; bl0[6]=t.z; bl0[7]=t.w;
                t = q1[0]; bl1[0]=t.x; bl1[1]=t.y; bl1[2]=t.z; bl1[3]=t.w;
                t = q1[1]; bl1[4]=t.x; bl1[5]=t.y; bl1[6]=t.z; bl1[7]=t.w;
            }
            #pragma unroll
            for (int j = 0; j < 8; j++) {
                mma_bf16(acc1[j], A1h[kt][0], A1h[kt][1], A1h[kt][2], A1h[kt][3], bh0[j], bh1[j]);
                mma_bf16(acc1[j], A1l[kt][0], A1l[kt][1], A1l[kt][2], A1l[kt][3], bh0[j], bh1[j]);
                mma_bf16(acc1[j], A1h[kt][0], A1h[kt][1], A1h[kt][2], A1h[kt][3], bl0[j], bl1[j]);
            }
        }

        float s0 = 0.f, q0s = 0.f, s1 = 0.f, q1s = 0.f;
        #pragma unroll
        for (int j = 0; j < 8; j++) {
            float2 b = b1p[c + 4 * j];
            acc1[j].x += b.x; acc1[j].y += b.y; acc1[j].z += b.x; acc1[j].w += b.y;
            s0 += acc1[j].x + acc1[j].y;
            q0s += acc1[j].x * acc1[j].x + acc1[j].y * acc1[j].y;
            s1 += acc1[j].z + acc1[j].w;
            q1s += acc1[j].z * acc1[j].z + acc1[j].w * acc1[j].w;
        }
        s0 += __shfl_xor_sync(0xffffffffu, s0, 1); s0 += __shfl_xor_sync(0xffffffffu, s0, 2);
        q0s += __shfl_xor_sync(0xffffffffu, q0s, 1); q0s += __shfl_xor_sync(0xffffffffu, q0s, 2);
        s1 += __shfl_xor_sync(0xffffffffu, s1, 1); s1 += __shfl_xor_sync(0xffffffffu, s1, 2);
        q1s += __shfl_xor_sync(0xffffffffu, q1s, 1); q1s += __shfl_xor_sync(0xffffffffu, q1s, 2);
        float mu0 = s0 * (1.f / 64.f), mu1 = s1 * (1.f / 64.f);
        float rstd0 = rsqrtf(fmaf(-mu0, mu0, q0s * (1.f / 64.f)) + 1e-5f);
        float rstd1 = rsqrtf(fmaf(-mu1, mu1, q1s * (1.f / 64.f)) + 1e-5f);
        #pragma unroll
        for (int j = 0; j < 8; j++) {
            float2 g = g1p[c + 4 * j], be = be1p[c + 4 * j];
            acc1[j].x = fmaxf(fmaf((acc1[j].x - mu0) * rstd0, g.x, be.x), 0.f);
            acc1[j].y = fmaxf(fmaf((acc1[j].y - mu0) * rstd0, g.y, be.y), 0.f);
            acc1[j].z = fmaxf(fmaf((acc1[j].z - mu1) * rstd1, g.x, be.x), 0.f);
            acc1[j].w = fmaxf(fmaf((acc1[j].w - mu1) * rstd1, g.y, be.y), 0.f);
        }

        uint32_t A2h[4][4], A2l[4][4];
        #pragma unroll
        for (int kt = 0; kt < 4; kt++) {
            F4 e = acc1[2 * kt], o = acc1[2 * kt + 1];
            float h;
            h = bf_hi(e.x); float h2 = bf_hi(e.y);
            A2h[kt][0] = bfpack(h, h2); A2l[kt][0] = bfpack(e.x - h, e.y - h2);
            h = bf_hi(e.z); h2 = bf_hi(e.w);
            A2h[kt][1] = bfpack(h, h2); A2l[kt][1] = bfpack(e.z - h, e.w - h2);
            h = bf_hi(o.x); h2 = bf_hi(o.y);
            A2h[kt][2] = bfpack(h, h2); A2l[kt][2] = bfpack(o.x - h, o.y - h2);
            h = bf_hi(o.z); h2 = bf_hi(o.w);
            A2h[kt][3] = bfpack(h, h2); A2l[kt][3] = bfpack(o.z - h, o.w - h2);
        }

        F4 acc2[4];
        #pragma unroll
        for (int j = 0; j < 4; j++) { acc2[j].x = acc2[j].y = acc2[j].z = acc2[j].w = 0.f; }
        #pragma unroll
        for (int kt = 0; kt < 4; kt++) {
            uint4 h0 = *(const uint4*)&W2fh[(kt * 2 + 0) * 384 + lane * 12];
            uint4 h1 = *(const uint4*)&W2fh[(kt * 2 + 1) * 384 + lane * 12];
            uint4 l0 = *(const uint4*)&W2fl[(kt * 2 + 0) * 384 + lane * 12];
            uint4 l1 = *(const uint4*)&W2fl[(kt * 2 + 1) * 384 + lane * 12];
            uint32_t bh0[4] = {h0.x, h0.y, h0.z, h0.w};
            uint32_t bh1[4] = {h1.x, h1.y, h1.z, h1.w};
            uint32_t bl0[4] = {l0.x, l0.y, l0.z, l0.w};
            uint32_t bl1[4] = {l1.x, l1.y, l1.z, l1.w};
            #pragma unroll
            for (int j = 0; j < 4; j++) {
                mma_bf16(acc2[j], A2h[kt][0], A2h[kt][1], A2h[kt][2], A2h[kt][3], bh0[j], bh1[j]);
                mma_bf16(acc2[j], A2l[kt][0], A2l[kt][1], A2l[kt][2], A2l[kt][3], bh0[j], bh1[j]);
                mma_bf16(acc2[j], A2h[kt][0], A2h[kt][1], A2h[kt][2], A2h[kt][3], bl0[j], bl1[j]);
            }
        }

        size_t orow = row0 + wid * 16 + r;
        #pragma unroll
        for (int j = 0; j < 4; j++) {
            float2 b = b2p[4 * j + c];
            int kth = j >> 1;
            float2 rx0 = (j & 1) ? xa2[kth] : xa0[kth];
            float2 rx1 = (j & 1) ? xa3[kth] : xa1[kth];
            float v00 = acc2[j].x + b.x + rx0.x, v01 = acc2[j].y + b.y + rx0.y;
            float v10 = acc2[j].z + b.x + rx1.x, v11 = acc2[j].w + b.y + rx1.y;
            *(uint32_t*)&sph[orow * 32 + 8 * j + 2 * c]       = h2pack(v00, v01);
            *(uint32_t*)&sph[(orow + 8) * 32 + 8 * j + 2 * c] = h2pack(v10, v11);
        }
    }
}

// ---------------------------------------------------------------------------
// K2 (fp16 m16n8k16, SINGLE PASS): out = tanh(adj_f16 @ sp_f16), fp32 accum.
// A frags load directly from fp16 adj (contiguous pairs); B staged via PRMT.
// ---------------------------------------------------------------------------
__global__ __launch_bounds__(256) void k2_mma(
    const __half* __restrict__ adjf, const __half* __restrict__ sph,
    float* __restrict__ out)
{
    __shared__ __align__(16) uint32_t Ahs[2048];
    __shared__ __align__(16) uint32_t Bhs[2560];

    int tid = threadIdx.x, lane = tid & 31, wid = tid >> 5;
    int n0  = blockIdx.x * 128;
    int bs0 = blockIdx.y * 4;
    int r = lane >> 2, c = lane & 3;

    F4 acc[4][4];
    #pragma unroll
    for (int u = 0; u < 4; u++)
        #pragma unroll
        for (int j = 0; j < 4; j++) { acc[u][j].x = acc[u][j].y = acc[u][j].z = acc[u][j].w = 0.f; }

    for (int mc = 0; mc < 512; mc += 32) {
        __syncthreads();
        // stage A: adj rows, fp16 pairs are frag words directly
        #pragma unroll
        for (int p = 0; p < 2; p++) {
            int i = p * 256 + tid;
            int n = i >> 2, seg = i & 3;
            size_t boff = ((size_t)(n0 + n) * 512 + mc) * 2 + seg * 16;
            uint4 vh = *(const uint4*)((const char*)adjf + boff);
            int w = n >> 4, rr = n & 15, rf = rr & 7, rh = rr >> 3, kt = seg >> 1;
            int base = (w * 2 + kt) * 128 + rf * 16;
            uint32_t ah[4] = {vh.x, vh.y, vh.z, vh.w};
            #pragma unroll
            for (int u = 0; u < 4; u++) {
                int kpl = (seg & 1) * 4 + u;
                int cc = kpl & 3, side = kpl >> 2;
                Ahs[base + cc * 4 + side * 2 + rh] = ah[u];
            }
        }
        // stage B: sp fp16, interleave row pairs via PRMT
        #pragma unroll
        for (int p = 0; p < 2; p++) {
            int u = p * 2 + (tid >> 7);
            int rem = tid & 127;
            int kp = rem >> 3, q = rem & 7, col0 = q * 4;
            const __half* s0 = &sph[((size_t)(bs0 + u) * 512 + mc + 2 * kp) * 32 + col0];
            uint2 A  = *(const uint2*)s0;
            uint2 Bv = *(const uint2*)(s0 + 32);
            int kt = kp >> 3, kpl = kp & 7, half = kpl >> 2, cc = kpl & 3;
            int bb = ((u * 2 + kt) * 2 + half) * 160 + cc * 40;
            int j0 = col0 >> 3, rr0v = col0 & 7;
            Bhs[bb + (rr0v + 0) * 4 + j0] = __byte_perm(A.x, Bv.x, 0x5410);
            Bhs[bb + (rr0v + 1) * 4 + j0] = __byte_perm(A.x, Bv.x, 0x7632);
            Bhs[bb + (rr0v + 2) * 4 + j0] = __byte_perm(A.y, Bv.y, 0x5410);
            Bhs[bb + (rr0v + 3) * 4 + j0] = __byte_perm(A.y, Bv.y, 0x7632);
        }
        __syncthreads();

        #pragma unroll
        for (int kt = 0; kt < 2; kt++) {
            uint4 Ah4 = *(const uint4*)&Ahs[(wid * 2 + kt) * 128 + lane * 4];
            #pragma unroll
            for (int u = 0; u < 4; u++) {
                int bb = ((u * 2 + kt) * 2) * 160 + c * 40 + r * 4;
                uint4 h0 = *(const uint4*)&Bhs[bb];
                uint4 h1 = *(const uint4*)&Bhs[bb + 160];
                uint32_t bh0[4] = {h0.x, h0.y, h0.z, h0.w};
                uint32_t bh1[4] = {h1.x, h1.y, h1.z, h1.w};
                #pragma unroll
                for (int j = 0; j < 4; j++)
                    mma_f16(acc[u][j], Ah4.x, Ah4.y, Ah4.z, Ah4.w, bh0[j], bh1[j]);
            }
        }
    }

    int c2 = c * 2;
    #pragma unroll
    for (int u = 0; u < 4; u++) {
        size_t bsrow = (size_t)(bs0 + u) * 512;
        #pragma unroll
        for (int j = 0; j < 4; j++) {
            int col  = j * 8 + c2;
            int row0 = n0 + wid * 16 + r;
            float2 v0 = { tanh_f(acc[u][j].x), tanh_f(acc[u][j].y) };
            float2 v1 = { tanh_f(acc[u][j].z), tanh_f(acc[u][j].w) };
            *(float2*)&out[(bsrow + row0)     * 32 + col] = v0;
            *(float2*)&out[(bsrow + row0 + 8) * 32 + col] = v1;
        }
    }
}

// ---------------------------------------------------------------------------
// K3 (tf32 3-pass): B fragment-pair prestage + 2 row-tiles/block. (unchanged)
// ---------------------------------------------------------------------------
#define K3_SMEM_FLOATS (2*4608 + 2*3168 + 96)

__global__ __launch_bounds__(256) void k3_mma(
    const float* __restrict__ tin, const float* __restrict__ g2,
    const float* __restrict__ be2, const float* __restrict__ w_ih,
    const float* __restrict__ b_ih, float* __restrict__ gi)
{
    extern __shared__ float smem[];
    float* Ah  = smem;
    float* Al  = Ah + 4608;
    float* Bfh = Al + 4608;
    float* Bfl = Bfh + 3168;
    float* bis = Bfl + 3168;

    int tid = threadIdx.x, lane = tid & 31, wid = tid >> 5;
    int r = lane >> 2, c = lane & 3;
    int mbase = wid * 16;

    #pragma unroll
    for (int p = 0; p < 12; p++) {
        int v = p * 256 + tid;
        int k = v & 31, col = v >> 5;
        float w = w_ih[col * 32 + k];
        float h = tf32_rna(w);
        int kt = k >> 3, cc = k & 3, reg = (k >> 2) & 1;
        int j = col >> 3, rr = col & 7;
        int addr = kt * 792 + j * 66 + (rr * 4 + cc) * 2 + reg;
        Bfh[addr] = h;
        Bfl[addr] = w - h;
    }
    if (tid < 96) bis[tid] = b_ih[tid];

    float g2v = g2[lane], be2v = be2[lane];

    for (int tile = 0; tile < 2; tile++) {
        size_t rr0 = (size_t)blockIdx.x * 256 + (size_t)tile * 128;
        if (tile) __syncthreads();

        #pragma unroll
        for (int q = 0; q < 16; q++) {
            int row = wid * 16 + q;
            float v = tin[(rr0 + row) * 32 + lane];
            float mu = warp_sum(v) * (1.f / 32.f);
            float d = v - mu;
            float var = warp_sum(d * d) * (1.f / 32.f);
            float ln = fmaf(d * rsqrtf(var + 1e-5f), g2v, be2v);
            float lh = tf32_rna(ln);
            Ah[row * 36 + lane] = lh;
            Al[row * 36 + lane] = ln - lh;
        }
        __syncthreads();

        F4 acc[12];
        #pragma unroll
        for (int j = 0; j < 12; j++) { acc[j].x = acc[j].y = acc[j].z = acc[j].w = 0.f; }

        #pragma unroll
        for (int kt = 0; kt < 4; kt++) {
            int kb = kt * 8;
            uint32_t ah0 = as_u(Ah[(mbase + r)     * 36 + kb + c]);
            uint32_t ah1 = as_u(Ah[(mbase + 8 + r) * 36 + kb + c]);
            uint32_t ah2 = as_u(Ah[(mbase + r)     * 36 + kb + 4 + c]);
            uint32_t ah3 = as_u(Ah[(mbase + 8 + r) * 36 + kb + 4 + c]);
            uint32_t al0 = as_u(Al[(mbase + r)     * 36 + kb + c]);
            uint32_t al1 = as_u(Al[(mbase + 8 + r) * 36 + kb + c]);
            uint32_t al2 = as_u(Al[(mbase + r)     * 36 + kb + 4 + c]);
            uint32_t al3 = as_u(Al[(mbase + 8 + r) * 36 + kb + 4 + c]);
            const float* bhp = &Bfh[kt * 792 + lane * 2];
            const float* blp = &Bfl[kt * 792 + lane * 2];
            #pragma unroll
            for (int j = 0; j < 12; j++) {
                float2 bh = *(const float2*)(bhp + j * 66);
                float2 bl = *(const float2*)(blp + j * 66);
                mma_tf32(acc[j], ah0, ah1, ah2, ah3, as_u(bh.x), as_u(bh.y));
                mma_tf32(acc[j], al0, al1, al2, al3, as_u(bh.x), as_u(bh.y));
                mma_tf32(acc[j], ah0, ah1, ah2, ah3, as_u(bl.x), as_u(bl.y));
            }
        }

        int c2 = c * 2;
        #pragma unroll
        for (int j = 0; j < 12; j++) {
            int col = j * 8 + c2;
            float2 bi = *(const float2*)&bis[col];
            size_t row0 = rr0 + mbase + r;
            float2 v0 = { acc[j].x + bi.x, acc[j].y + bi.y };
            float2 v1 = { acc[j].z + bi.x, acc[j].w + bi.y };
            *(float2*)&gi[row0 * 96 + col]       = v0;
            *(float2*)&gi[(row0 + 8) * 96 + col] = v1;
        }
    }
}

// ---------------------------------------------------------------------------
// K4 (R11 version): 2 sequences per warp, single wave. (unchanged)
// ---------------------------------------------------------------------------
__global__ __launch_bounds__(128, 4) void k4_gru(
    const float* __restrict__ gi, const float* __restrict__ w_hh,
    const float* __restrict__ b_hh, float* __restrict__ out)
{
    __shared__ float gbuf[4][8][192];

    int tid = threadIdx.x, lane = tid & 31, wr = tid >> 5;
    int p = blockIdx.x * 4 + wr;
    int bn = 2 * p;
    int b = bn >> 9, n = bn & 511;

    float w0[32], w1[32], w2[32];
    #pragma unroll
    for (int m = 0; m < 8; m++) {
        float4 a = ((const float4*)(w_hh + (size_t)lane * 32))[m];
        float4 cc = ((const float4*)(w_hh + (size_t)(lane + 32) * 32))[m];
        float4 d = ((const float4*)(w_hh + (size_t)(lane + 64) * 32))[m];
        w0[4*m+0]=a.x;  w0[4*m+1]=a.y;  w0[4*m+2]=a.z;  w0[4*m+3]=a.w;
        w1[4*m+0]=cc.x; w1[4*m+1]=cc.y; w1[4*m+2]=cc.z; w1[4*m+3]=cc.w;
        w2[4*m+0]=d.x;  w2[4*m+1]=d.y;  w2[4*m+2]=d.z;  w2[4*m+3]=d.w;
    }
    float bh0 = b_hh[lane], bh1 = b_hh[lane + 32], bh2 = b_hh[lane + 64];

    const size_t tstride = (size_t)512 * 96;
    const float* gA = gi + ((size_t)(b * 256) * 512 + n) * 96;

    #pragma unroll
    for (int s = 0; s < 7; s++) {
        const float* src = gA + (size_t)s * tstride;
        uint32_t d = (uint32_t)__cvta_generic_to_shared(&gbuf[wr][s][lane]);
        cp4(d,       src + lane);
        cp4(d + 128, src + lane + 32);
        cp4(d + 256, src + lane + 64);
        cp4(d + 384, src + lane + 96);
        cp4(d + 512, src + lane + 128);
        cp4(d + 640, src + lane + 160);
        asm volatile("cp.async.commit_group;" ::: "memory");
    }

    float hA = 0.f, hB = 0.f;
    ull hp = 0;
    float* outp = out + ((size_t)(b * 256) * 512 + n) * 32 + lane;

    for (int t = 0; t < 256; t++) {
        if (t + 7 < 256) {
            const float* src = gA + (size_t)(t + 7) * tstride;
            uint32_t d = (uint32_t)__cvta_generic_to_shared(&gbuf[wr][(t + 7) & 7][lane]);
            cp4(d,       src + lane);
            cp4(d + 128, src + lane + 32);
            cp4(d + 256, src + lane + 64);
            cp4(d + 384, src + lane + 96);
            cp4(d + 512, src + lane + 128);
            cp4(d + 640, src + lane + 160);
        }
        asm volatile("cp.async.commit_group;" ::: "memory");
        asm volatile("cp.async.wait_group 7;" ::: "memory");

        int s = t & 7;
        float qA0 = gbuf[wr][s][lane];
        float qA1 = gbuf[wr][s][lane + 32];
        float qA2 = gbuf[wr][s][lane + 64];
        float qB0 = gbuf[wr][s][lane + 96];
        float qB1 = gbuf[wr][s][lane + 128];
        float qB2 = gbuf[wr][s][lane + 160];

        float a0A = bh0, a1A = bh1, a2A = bh2;
        float a0B = bh0, a1B = bh1, a2B = bh2;
        float e0A = 0.f, e1A = 0.f, e2A = 0.f;
        float e0B = 0.f, e1B = 0.f, e2B = 0.f;
        #pragma unroll
        for (int jj = 0; jj < 16; jj++) {
            float2 hj = unpack2(__shfl_sync(0xffffffffu, hp, jj));
            float2 hk = unpack2(__shfl_sync(0xffffffffu, hp, jj + 16));
            a0A = fmaf(hj.x, w0[jj], a0A);       a0B = fmaf(hj.y, w0[jj], a0B);
            e0A = fmaf(hk.x, w0[jj + 16], e0A);  e0B = fmaf(hk.y, w0[jj + 16], e0B);
            a1A = fmaf(hj.x, w1[jj], a1A);       a1B = fmaf(hj.y, w1[jj], a1B);
            e1A = fmaf(hk.x, w1[jj + 16], e1A);  e1B = fmaf(hk.y, w1[jj + 16], e1B);
            a2A = fmaf(hj.x, w2[jj], a2A);       a2B = fmaf(hj.y, w2[jj], a2B);
            e2A = fmaf(hk.x, w2[jj + 16], e2A);  e2B = fmaf(hk.y, w2[jj + 16], e2B);
        }
        a0A += e0A; a1A += e1A; a2A += e2A;
        a0B += e0B; a1B += e1B; a2B += e2B;

        float rgA = sigmoid_f(qA0 + a0A);
        float zgA = sigmoid_f(qA1 + a1A);
        float ngA = tanh_f(fmaf(rgA, a2A, qA2));
        hA = fmaf(zgA, hA - ngA, ngA);

        float rgB = sigmoid_f(qB0 + a0B);
        float zgB = sigmoid_f(qB1 + a1B);
        float ngB = tanh_f(fmaf(rgB, a2B, qB2));
        hB = fmaf(zgB, hB - ngB, ngB);

        outp[0]  = hA;
        outp[32] = hB;
        outp += (size_t)512 * 32;

        hp = pack2(hA, hB);
    }
}

// ---------------------------------------------------------------------------
extern "C" void kernel_launch(void* const* d_in, const int* in_sizes, int n_in,
                              void* d_out, int out_size)
{
    (void)in_sizes; (void)n_in; (void)out_size;
    const float* x    = (const float*)d_in[0];
    const float* adj  = (const float*)d_in[1];
    const float* W1   = (const float*)d_in[2];
    const float* b1   = (const float*)d_in[3];
    const float* g1   = (const float*)d_in[4];
    const float* be1  = (const float*)d_in[5];
    const float* W2   = (const float*)d_in[6];
    const float* b2   = (const float*)d_in[7];
    const float* g2   = (const float*)d_in[8];
    const float* be2  = (const float*)d_in[9];
    const float* w_ih = (const float*)d_in[10];
    const float* w_hh = (const float*)d_in[11];
    const float* b_ih = (const float*)d_in[12];
    const float* b_hh = (const float*)d_in[13];
    float* out = (float*)d_out;

    __half *sph, *af;
    float *th, *gv;
    cudaGetSymbolAddress((void**)&sph, g_sph);
    cudaGetSymbolAddress((void**)&th, g_tanh);
    cudaGetSymbolAddress((void**)&gv, g_gi);
    cudaGetSymbolAddress((void**)&af, g_adjf);

    static int smem_set = 0;
    if (!smem_set) {
        cudaFuncSetAttribute(k3_mma, cudaFuncAttributeMaxDynamicSharedMemorySize,
                             K3_SMEM_FLOATS * (int)sizeof(float));
        smem_set = 1;
    }

    k0_split<<<(Nn * Nn) / 256, 256>>>(adj, af);
    k1_mma<<<RTOT / 256, 256>>>(x, W1, b1, g1, be1, W2, b2, sph);
    k2_mma<<<dim3(4, BS / 4), 256>>>(af, sph, th);
    k3_mma<<<RTOT / 256, 256, K3_SMEM_FLOATS * sizeof(float)>>>(th, g2, be2, w_ih, b_ih, gv);
    k4_gru<<<BN / 8, 128>>>(gv, w_hh, b_hh, out);
}

// round 17
// speedup vs baseline: 1.4145x; 1.0938x over previous
#include <cuda_runtime.h>
#include <cuda_bf16.h>
#include <cuda_fp16.h>
#include <math.h>
#include <stdint.h>

#define Bb   8
#define Ss   256
#define Nn   512
#define Ii   32
#define HH   64
#define Oo   32
#define BS   (Bb*Ss)                 // 2048
#define RTOT (BS*Nn)                 // 1,048,576 rows
#define BN   (Bb*Nn)                 // 4096 GRU sequences

typedef unsigned long long ull;

// Scratch
__device__ __half    g_sph [(size_t)RTOT * Oo];   // 67 MB: sp fp16
__device__ __half    g_th  [(size_t)RTOT * Oo];   // 67 MB: tanh output fp16
__device__ uint32_t  g_gi  [(size_t)RTOT * 48];   // 201 MB: fp16 gates (48 u32/row)
__device__ __half    g_adjf[Nn * Nn];             // adj fp16

__device__ __forceinline__ float warp_sum(float v) {
    #pragma unroll
    for (int o = 16; o > 0; o >>= 1) v += __shfl_xor_sync(0xffffffffu, v, o);
    return v;
}
__device__ __forceinline__ float sigmoid_f(float x) {
    return __fdividef(1.f, 1.f + __expf(-x));
}
__device__ __forceinline__ float tanh_f(float x) {
    float ax = fabsf(x);
    float e  = __expf(-2.f * ax);
    float t  = (1.f - e) * __fdividef(1.f, 1.f + e);
    return copysignf(t, x);
}
__device__ __forceinline__ uint32_t as_u(float f) { return __float_as_uint(f); }
__device__ __forceinline__ float bf_hi(float v) {
    return __bfloat162float(__float2bfloat16_rn(v));
}
__device__ __forceinline__ uint32_t bfpack(float a, float b) {
    __nv_bfloat162 t = __floats2bfloat162_rn(a, b);
    return *reinterpret_cast<uint32_t*>(&t);
}
__device__ __forceinline__ uint32_t h2pack(float a, float b) {
    __half2 t = __floats2half2_rn(a, b);
    return *reinterpret_cast<uint32_t*>(&t);
}
__device__ __forceinline__ ull pack2(float lo, float hi) {
    ull r; asm("mov.b64 %0,{%1,%2};" : "=l"(r) : "f"(lo), "f"(hi)); return r;
}
__device__ __forceinline__ float2 unpack2(ull v) {
    float2 f; asm("mov.b64 {%0,%1},%2;" : "=f"(f.x), "=f"(f.y) : "l"(v)); return f;
}

struct F4 { float x, y, z, w; };
__device__ __forceinline__ void mma_bf16(F4& d,
    uint32_t a0, uint32_t a1, uint32_t a2, uint32_t a3, uint32_t b0, uint32_t b1)
{
    asm volatile(
        "mma.sync.aligned.m16n8k16.row.col.f32.bf16.bf16.f32 "
        "{%0,%1,%2,%3},{%4,%5,%6,%7},{%8,%9},{%0,%1,%2,%3};"
        : "+f"(d.x), "+f"(d.y), "+f"(d.z), "+f"(d.w)
        : "r"(a0), "r"(a1), "r"(a2), "r"(a3), "r"(b0), "r"(b1));
}
__device__ __forceinline__ void mma_f16(F4& d,
    uint32_t a0, uint32_t a1, uint32_t a2, uint32_t a3, uint32_t b0, uint32_t b1)
{
    asm volatile(
        "mma.sync.aligned.m16n8k16.row.col.f32.f16.f16.f32 "
        "{%0,%1,%2,%3},{%4,%5,%6,%7},{%8,%9},{%0,%1,%2,%3};"
        : "+f"(d.x), "+f"(d.y), "+f"(d.z), "+f"(d.w)
        : "r"(a0), "r"(a1), "r"(a2), "r"(a3), "r"(b0), "r"(b1));
}
__device__ __forceinline__ void cp4(uint32_t dst, const void* src) {
    asm volatile("cp.async.ca.shared.global [%0], [%1], 4;" :: "r"(dst), "l"(src));
}

// ---------------------------------------------------------------------------
// K0: adj -> fp16
// ---------------------------------------------------------------------------
__global__ __launch_bounds__(256) void k0_split(
    const float* __restrict__ adj, __half* __restrict__ af)
{
    int i = blockIdx.x * 256 + threadIdx.x;
    af[i] = __float2half_rn(adj[i]);
}

// ---------------------------------------------------------------------------
// K1 (bf16 MMA, 3-pass): 2 row-tiles per block; stores sp as fp16. (R15)
// ---------------------------------------------------------------------------
__global__ __launch_bounds__(256) void k1_mma(
    const float* __restrict__ x,  const float* __restrict__ W1,
    const float* __restrict__ b1, const float* __restrict__ g1,
    const float* __restrict__ be1,const float* __restrict__ W2,
    const float* __restrict__ b2, __half* __restrict__ sph)
{
    __shared__ __align__(16) uint32_t W1fh[1536], W1fl[1536];
    __shared__ __align__(16) uint32_t W2fh[3072], W2fl[3072];
    __shared__ float2 b1p[32], g1p[32], be1p[32], b2p[16];

    int tid = threadIdx.x, lane = tid & 31, wid = tid >> 5;
    int r = lane >> 2, c = lane & 3;

    #pragma unroll
    for (int p = 0; p < 4; p++) {
        int i = p * 256 + tid;
        int kp = i >> 6, n = i & 63;
        float wa = W1[(2 * kp) * 64 + n], wb = W1[(2 * kp + 1) * 64 + n];
        float ha = bf_hi(wa), hb = bf_hi(wb);
        int kt = kp >> 3, kpl = kp & 7, half = kpl >> 2, cc = kpl & 3;
        int j = n >> 3, rr = n & 7;
        int idx = (kt * 2 + half) * 384 + (rr * 4 + cc) * 12 + j;
        W1fh[idx] = bfpack(ha, hb);
        W1fl[idx] = bfpack(wa - ha, wb - hb);
    }
    #pragma unroll
    for (int p = 0; p < 4; p++) {
        int i = p * 256 + tid;
        int kp = i >> 5, n = i & 31;
        float wa = W2[(2 * kp) * 32 + n], wb = W2[(2 * kp + 1) * 32 + n];
        float ha = bf_hi(wa), hb = bf_hi(wb);
        int kt = kp >> 3, kpl = kp & 7, half = kpl >> 2, cc = kpl & 3;
        int j = n >> 3, rr = n & 7;
        int idx = (kt * 2 + half) * 384 + (rr * 4 + cc) * 12 + j;
        W2fh[idx] = bfpack(ha, hb);
        W2fl[idx] = bfpack(wa - ha, wb - hb);
    }
    if (tid < 32) {
        b1p[tid]  = ((const float2*)b1)[tid];
        g1p[tid]  = ((const float2*)g1)[tid];
        be1p[tid] = ((const float2*)be1)[tid];
        if (tid < 16) b2p[tid] = ((const float2*)b2)[tid];
    }
    __syncthreads();

    for (int tile = 0; tile < 2; tile++) {
        size_t row0 = (size_t)blockIdx.x * 256 + (size_t)tile * 128;

        const float* xr  = x + (row0 + wid * 16 + r) * 32;
        const float* xr8 = xr + 8 * 32;
        float2 xa0[2], xa1[2], xa2[2], xa3[2];
        uint32_t A1h[2][4], A1l[2][4];
        #pragma unroll
        for (int kt = 0; kt < 2; kt++) {
            xa0[kt] = ((const float2*)xr)[kt * 8 + c];
            xa2[kt] = ((const float2*)xr)[kt * 8 + 4 + c];
            xa1[kt] = ((const float2*)xr8)[kt * 8 + c];
            xa3[kt] = ((const float2*)xr8)[kt * 8 + 4 + c];
            float h;
            h = bf_hi(xa0[kt].x); float h2 = bf_hi(xa0[kt].y);
            A1h[kt][0] = bfpack(h, h2); A1l[kt][0] = bfpack(xa0[kt].x - h, xa0[kt].y - h2);
            h = bf_hi(xa1[kt].x); h2 = bf_hi(xa1[kt].y);
            A1h[kt][1] = bfpack(h, h2); A1l[kt][1] = bfpack(xa1[kt].x - h, xa1[kt].y - h2);
            h = bf_hi(xa2[kt].x); h2 = bf_hi(xa2[kt].y);
            A1h[kt][2] = bfpack(h, h2); A1l[kt][2] = bfpack(xa2[kt].x - h, xa2[kt].y - h2);
            h = bf_hi(xa3[kt].x); h2 = bf_hi(xa3[kt].y);
            A1h[kt][3] = bfpack(h, h2); A1l[kt][3] = bfpack(xa3[kt].x - h, xa3[kt].y - h2);
        }

        F4 acc1[8];
        #pragma unroll
        for (int j = 0; j < 8; j++) { acc1[j].x = acc1[j].y = acc1[j].z = acc1[j].w = 0.f; }
        #pragma unroll
        for (int kt = 0; kt < 2; kt++) {
            uint32_t bh0[8], bh1[8], bl0[8], bl1[8];
            {
                const uint4* p0 = (const uint4*)&W1fh[(kt * 2 + 0) * 384 + lane * 12];
                const uint4* p1 = (const uint4*)&W1fh[(kt * 2 + 1) * 384 + lane * 12];
                const uint4* q0 = (const uint4*)&W1fl[(kt * 2 + 0) * 384 + lane * 12];
                const uint4* q1 = (const uint4*)&W1fl[(kt * 2 + 1) * 384 + lane * 12];
                uint4 t;
                t = p0[0]; bh0[0]=t.x; bh0[1]=t.y; bh0[2]=t.z; bh0[3]=t.w;
                t = p0[1]; bh0[4]=t.x; bh0[5]=t.y; bh0[6]=t.z; bh0[7]=t.w;
                t = p1[0]; bh1[0]=t.x; bh1[1]=t.y; bh1[2]=t.z; bh1[3]=t.w;
                t = p1[1]; bh1[4]=t.x; bh1[5]=t.y; bh1[6]=t.z; bh1[7]=t.w;
                t = q0[0]; bl0[0]=t.x; bl0[1]=t.y; bl0[2]=t.z; bl0[3]=t.w;
                t = q0[1]; bl0[4]=t.x; bl0[5]=t.y; bl0[6]=t.z; bl0[7]=t.w;
                t = q1[0]; bl1[0]=t.x; bl1[1]=t.y; bl1[2]=t.z; bl1[3]=t.w;
                t = q1[1]; bl1[4]=t.x; bl1[5]=t.y; bl1[6]=t.z; bl1[7]=t.w;
            }
            #pragma unroll
            for (int j = 0; j < 8; j++) {
                mma_bf16(acc1[j], A1h[kt][0], A1h[kt][1], A1h[kt][2], A1h[kt][3], bh0[j], bh1[j]);
                mma_bf16(acc1[j], A1l[kt][0], A1l[kt][1], A1l[kt][2], A1l[kt][3], bh0[j], bh1[j]);
                mma_bf16(acc1[j], A1h[kt][0], A1h[kt][1], A1h[kt][2], A1h[kt][3], bl0[j], bl1[j]);
            }
        }

        float s0 = 0.f, q0s = 0.f, s1 = 0.f, q1s = 0.f;
        #pragma unroll
        for (int j = 0; j < 8; j++) {
            float2 b = b1p[c + 4 * j];
            acc1[j].x += b.x; acc1[j].y += b.y; acc1[j].z += b.x; acc1[j].w += b.y;
            s0 += acc1[j].x + acc1[j].y;
            q0s += acc1[j].x * acc1[j].x + acc1[j].y * acc1[j].y;
            s1 += acc1[j].z + acc1[j].w;
            q1s += acc1[j].z * acc1[j].z + acc1[j].w * acc1[j].w;
        }
        s0 += __shfl_xor_sync(0xffffffffu, s0, 1); s0 += __shfl_xor_sync(0xffffffffu, s0, 2);
        q0s += __shfl_xor_sync(0xffffffffu, q0s, 1); q0s += __shfl_xor_sync(0xffffffffu, q0s, 2);
        s1 += __shfl_xor_sync(0xffffffffu, s1, 1); s1 += __shfl_xor_sync(0xffffffffu, s1, 2);
        q1s += __shfl_xor_sync(0xffffffffu, q1s, 1); q1s += __shfl_xor_sync(0xffffffffu, q1s, 2);
        float mu0 = s0 * (1.f / 64.f), mu1 = s1 * (1.f / 64.f);
        float rstd0 = rsqrtf(fmaf(-mu0, mu0, q0s * (1.f / 64.f)) + 1e-5f);
        float rstd1 = rsqrtf(fmaf(-mu1, mu1, q1s * (1.f / 64.f)) + 1e-5f);
        #pragma unroll
        for (int j = 0; j < 8; j++) {
            float2 g = g1p[c + 4 * j], be = be1p[c + 4 * j];
            acc1[j].x = fmaxf(fmaf((acc1[j].x - mu0) * rstd0, g.x, be.x), 0.f);
            acc1[j].y = fmaxf(fmaf((acc1[j].y - mu0) * rstd0, g.y, be.y), 0.f);
            acc1[j].z = fmaxf(fmaf((acc1[j].z - mu1) * rstd1, g.x, be.x), 0.f);
            acc1[j].w = fmaxf(fmaf((acc1[j].w - mu1) * rstd1, g.y, be.y), 0.f);
        }

        uint32_t A2h[4][4], A2l[4][4];
        #pragma unroll
        for (int kt = 0; kt < 4; kt++) {
            F4 e = acc1[2 * kt], o = acc1[2 * kt + 1];
            float h;
            h = bf_hi(e.x); float h2 = bf_hi(e.y);
            A2h[kt][0] = bfpack(h, h2); A2l[kt][0] = bfpack(e.x - h, e.y - h2);
            h = bf_hi(e.z); h2 = bf_hi(e.w);
            A2h[kt][1] = bfpack(h, h2); A2l[kt][1] = bfpack(e.z - h, e.w - h2);
            h = bf_hi(o.x); h2 = bf_hi(o.y);
            A2h[kt][2] = bfpack(h, h2); A2l[kt][2] = bfpack(o.x - h, o.y - h2);
            h = bf_hi(o.z); h2 = bf_hi(o.w);
            A2h[kt][3] = bfpack(h, h2); A2l[kt][3] = bfpack(o.z - h, o.w - h2);
        }

        F4 acc2[4];
        #pragma unroll
        for (int j = 0; j < 4; j++) { acc2[j].x = acc2[j].y = acc2[j].z = acc2[j].w = 0.f; }
        #pragma unroll
        for (int kt = 0; kt < 4; kt++) {
            uint4 h0 = *(const uint4*)&W2fh[(kt * 2 + 0) * 384 + lane * 12];
            uint4 h1 = *(const uint4*)&W2fh[(kt * 2 + 1) * 384 + lane * 12];
            uint4 l0 = *(const uint4*)&W2fl[(kt * 2 + 0) * 384 + lane * 12];
            uint4 l1 = *(const uint4*)&W2fl[(kt * 2 + 1) * 384 + lane * 12];
            uint32_t bh0[4] = {h0.x, h0.y, h0.z, h0.w};
            uint32_t bh1[4] = {h1.x, h1.y, h1.z, h1.w};
            uint32_t bl0[4] = {l0.x, l0.y, l0.z, l0.w};
            uint32_t bl1[4] = {l1.x, l1.y, l1.z, l1.w};
            #pragma unroll
            for (int j = 0; j < 4; j++) {
                mma_bf16(acc2[j], A2h[kt][0], A2h[kt][1], A2h[kt][2], A2h[kt][3], bh0[j], bh1[j]);
                mma_bf16(acc2[j], A2l[kt][0], A2l[kt][1], A2l[kt][2], A2l[kt][3], bh0[j], bh1[j]);
                mma_bf16(acc2[j], A2h[kt][0], A2h[kt][1], A2h[kt][2], A2h[kt][3], bl0[j], bl1[j]);
            }
        }

        size_t orow = row0 + wid * 16 + r;
        #pragma unroll
        for (int j = 0; j < 4; j++) {
            float2 b = b2p[4 * j + c];
            int kth = j >> 1;
            float2 rx0 = (j & 1) ? xa2[kth] : xa0[kth];
            float2 rx1 = (j & 1) ? xa3[kth] : xa1[kth];
            float v00 = acc2[j].x + b.x + rx0.x, v01 = acc2[j].y + b.y + rx0.y;
            float v10 = acc2[j].z + b.x + rx1.x, v11 = acc2[j].w + b.y + rx1.y;
            *(uint32_t*)&sph[orow * 32 + 8 * j + 2 * c]       = h2pack(v00, v01);
            *(uint32_t*)&sph[(orow + 8) * 32 + 8 * j + 2 * c] = h2pack(v10, v11);
        }
    }
}

// ---------------------------------------------------------------------------
// K2 (fp16 single-pass, R15) — now writes th as fp16.
// ---------------------------------------------------------------------------
__global__ __launch_bounds__(256) void k2_mma(
    const __half* __restrict__ adjf, const __half* __restrict__ sph,
    __half* __restrict__ th)
{
    __shared__ __align__(16) uint32_t Ahs[2048];
    __shared__ __align__(16) uint32_t Bhs[2560];

    int tid = threadIdx.x, lane = tid & 31, wid = tid >> 5;
    int n0  = blockIdx.x * 128;
    int bs0 = blockIdx.y * 4;
    int r = lane >> 2, c = lane & 3;

    F4 acc[4][4];
    #pragma unroll
    for (int u = 0; u < 4; u++)
        #pragma unroll
        for (int j = 0; j < 4; j++) { acc[u][j].x = acc[u][j].y = acc[u][j].z = acc[u][j].w = 0.f; }

    for (int mc = 0; mc < 512; mc += 32) {
        __syncthreads();
        #pragma unroll
        for (int p = 0; p < 2; p++) {
            int i = p * 256 + tid;
            int n = i >> 2, seg = i & 3;
            size_t boff = ((size_t)(n0 + n) * 512 + mc) * 2 + seg * 16;
            uint4 vh = *(const uint4*)((const char*)adjf + boff);
            int w = n >> 4, rr = n & 15, rf = rr & 7, rh = rr >> 3, kt = seg >> 1;
            int base = (w * 2 + kt) * 128 + rf * 16;
            uint32_t ah[4] = {vh.x, vh.y, vh.z, vh.w};
            #pragma unroll
            for (int u = 0; u < 4; u++) {
                int kpl = (seg & 1) * 4 + u;
                int cc = kpl & 3, side = kpl >> 2;
                Ahs[base + cc * 4 + side * 2 + rh] = ah[u];
            }
        }
        #pragma unroll
        for (int p = 0; p < 2; p++) {
            int u = p * 2 + (tid >> 7);
            int rem = tid & 127;
            int kp = rem >> 3, q = rem & 7, col0 = q * 4;
            const __half* s0 = &sph[((size_t)(bs0 + u) * 512 + mc + 2 * kp) * 32 + col0];
            uint2 A  = *(const uint2*)s0;
            uint2 Bv = *(const uint2*)(s0 + 32);
            int kt = kp >> 3, kpl = kp & 7, half = kpl >> 2, cc = kpl & 3;
            int bb = ((u * 2 + kt) * 2 + half) * 160 + cc * 40;
            int j0 = col0 >> 3, rr0v = col0 & 7;
            Bhs[bb + (rr0v + 0) * 4 + j0] = __byte_perm(A.x, Bv.x, 0x5410);
            Bhs[bb + (rr0v + 1) * 4 + j0] = __byte_perm(A.x, Bv.x, 0x7632);
            Bhs[bb + (rr0v + 2) * 4 + j0] = __byte_perm(A.y, Bv.y, 0x5410);
            Bhs[bb + (rr0v + 3) * 4 + j0] = __byte_perm(A.y, Bv.y, 0x7632);
        }
        __syncthreads();

        #pragma unroll
        for (int kt = 0; kt < 2; kt++) {
            uint4 Ah4 = *(const uint4*)&Ahs[(wid * 2 + kt) * 128 + lane * 4];
            #pragma unroll
            for (int u = 0; u < 4; u++) {
                int bb = ((u * 2 + kt) * 2) * 160 + c * 40 + r * 4;
                uint4 h0 = *(const uint4*)&Bhs[bb];
                uint4 h1 = *(const uint4*)&Bhs[bb + 160];
                uint32_t bh0[4] = {h0.x, h0.y, h0.z, h0.w};
                uint32_t bh1[4] = {h1.x, h1.y, h1.z, h1.w};
                #pragma unroll
                for (int j = 0; j < 4; j++)
                    mma_f16(acc[u][j], Ah4.x, Ah4.y, Ah4.z, Ah4.w, bh0[j], bh1[j]);
            }
        }
    }

    int c2 = c * 2;
    #pragma unroll
    for (int u = 0; u < 4; u++) {
        size_t bsrow = (size_t)(bs0 + u) * 512;
        #pragma unroll
        for (int j = 0; j < 4; j++) {
            int col  = j * 8 + c2;
            int row0 = n0 + wid * 16 + r;
            *(uint32_t*)&th[(bsrow + row0)     * 32 + col] =
                h2pack(tanh_f(acc[u][j].x), tanh_f(acc[u][j].y));
            *(uint32_t*)&th[(bsrow + row0 + 8) * 32 + col] =
                h2pack(tanh_f(acc[u][j].z), tanh_f(acc[u][j].w));
        }
    }
}

// ---------------------------------------------------------------------------
// K3 (NEW, fp16 single-pass): LN32 (fp32 math) -> fp16 A frags; w_ih fp16 B
// frags; gi = ln @ w_ih^T + b_ih stored as packed fp16 (48 u32/row:
// slots[0..31] = half2(q0[o], q1[o]); slots[32..47] = half2(q2[2i],q2[2i+1])).
// 24 MMAs per warp-tile (was 144). 2 row-tiles per block.
// ---------------------------------------------------------------------------
__global__ __launch_bounds__(256) void k3_mma(
    const __half* __restrict__ tin, const float* __restrict__ g2,
    const float* __restrict__ be2, const float* __restrict__ w_ih,
    const float* __restrict__ b_ih, uint32_t* __restrict__ gi)
{
    __shared__ uint16_t lnh[128][34];
    __shared__ __align__(16) uint32_t Ahs[2048];
    __shared__ __align__(16) uint32_t Bf[1664];   // [(kt*2+half)*416 + cc*104 + col]
    __shared__ float bis[96];

    int tid = threadIdx.x, lane = tid & 31, wid = tid >> 5;
    int r = lane >> 2, c = lane & 3;

    // stage B: w_ih fp16 frag words (k-pairs contiguous in w_ih rows)
    #pragma unroll
    for (int p = 0; p < 6; p++) {
        int idx = p * 256 + tid;           // < 1536
        int kp = idx & 15, col = idx >> 4;
        float2 w = *(const float2*)&w_ih[col * 32 + 2 * kp];
        int kt = kp >> 3, kpl = kp & 7, half = kpl >> 2, cc = kpl & 3;
        Bf[(kt * 2 + half) * 416 + cc * 104 + col] = h2pack(w.x, w.y);
    }
    if (tid < 96) bis[tid] = b_ih[tid];

    float g2v = g2[lane], be2v = be2[lane];

    for (int tile = 0; tile < 2; tile++) {
        size_t rr0 = (size_t)blockIdx.x * 256 + (size_t)tile * 128;
        if (tile) __syncthreads();

        // LN per row (fp32 math on fp16 input), store fp16
        #pragma unroll
        for (int q = 0; q < 16; q++) {
            int row = wid * 16 + q;
            float v = __half2float(tin[(rr0 + row) * 32 + lane]);
            float mu = warp_sum(v) * (1.f / 32.f);
            float d = v - mu;
            float var = warp_sum(d * d) * (1.f / 32.f);
            float ln = fmaf(d * rsqrtf(var + 1e-5f), g2v, be2v);
            lnh[row][lane] = __half_as_ushort(__float2half_rn(ln));
        }
        __syncthreads();

        // build A frags (u32 = contiguous fp16 pair in a row)
        #pragma unroll
        for (int p = 0; p < 8; p++) {
            int idx = p * 256 + tid;        // < 2048
            int row = idx >> 4, kp = idx & 15;
            uint32_t word = *(const uint32_t*)&lnh[row][2 * kp];
            int w = row >> 4, rf = row & 7, rh = (row >> 3) & 1;
            int kt = kp >> 3, kpl = kp & 7, half = kpl >> 2, cc = kpl & 3;
            Ahs[(w * 2 + kt) * 128 + rf * 16 + cc * 4 + half * 2 + rh] = word;
        }
        __syncthreads();

        F4 acc[12];
        #pragma unroll
        for (int j = 0; j < 12; j++) { acc[j].x = acc[j].y = acc[j].z = acc[j].w = 0.f; }

        #pragma unroll
        for (int kt = 0; kt < 2; kt++) {
            uint4 Ah4 = *(const uint4*)&Ahs[(wid * 2 + kt) * 128 + lane * 4];
            const uint32_t* b0p = &Bf[(kt * 2 + 0) * 416 + c * 104 + r];
            const uint32_t* b1p = &Bf[(kt * 2 + 1) * 416 + c * 104 + r];
            #pragma unroll
            for (int j = 0; j < 12; j++) {
                uint32_t b0 = b0p[j * 8];
                uint32_t b1 = b1p[j * 8];
                mma_f16(acc[j], Ah4.x, Ah4.y, Ah4.z, Ah4.w, b0, b1);
            }
        }

        // epilogue: + b_ih, packed fp16 store
        size_t row0 = rr0 + wid * 16 + r;
        uint32_t* g0 = gi + row0 * 48;
        uint32_t* g8 = gi + (row0 + 8) * 48;
        #pragma unroll
        for (int j = 0; j < 4; j++) {
            float2 br = *(const float2*)&bis[8 * j + 2 * c];
            float2 bz = *(const float2*)&bis[32 + 8 * j + 2 * c];
            float2 bn = *(const float2*)&bis[64 + 8 * j + 2 * c];
            F4 gr = acc[j], gz = acc[j + 4], gn = acc[j + 8];
            uint2 w0 = { h2pack(gr.x + br.x, gz.x + bz.x),
                         h2pack(gr.y + br.y, gz.y + bz.y) };
            uint2 w8 = { h2pack(gr.z + br.x, gz.z + bz.x),
                         h2pack(gr.w + br.y, gz.w + bz.y) };
            *(uint2*)&g0[8 * j + 2 * c] = w0;
            *(uint2*)&g8[8 * j + 2 * c] = w8;
            g0[32 + 4 * j + c] = h2pack(gn.x + bn.x, gn.y + bn.y);
            g8[32 + 4 * j + c] = h2pack(gn.z + bn.x, gn.w + bn.y);
        }
    }
}

// ---------------------------------------------------------------------------
// K4: 2 sequences per warp, single wave; gi is packed fp16 (48 u32/row).
// ---------------------------------------------------------------------------
__global__ __launch_bounds__(128, 4) void k4_gru(
    const uint32_t* __restrict__ gi, const float* __restrict__ w_hh,
    const float* __restrict__ b_hh, float* __restrict__ out)
{
    __shared__ uint32_t gbuf[4][8][96];   // [warp][stage][seqA 48 | seqB 48]

    int tid = threadIdx.x, lane = tid & 31, wr = tid >> 5;
    int p = blockIdx.x * 4 + wr;
    int bn = 2 * p;
    int b = bn >> 9, n = bn & 511;

    float w0[32], w1[32], w2[32];
    #pragma unroll
    for (int m = 0; m < 8; m++) {
        float4 a = ((const float4*)(w_hh + (size_t)lane * 32))[m];
        float4 cc = ((const float4*)(w_hh + (size_t)(lane + 32) * 32))[m];
        float4 d = ((const float4*)(w_hh + (size_t)(lane + 64) * 32))[m];
        w0[4*m+0]=a.x;  w0[4*m+1]=a.y;  w0[4*m+2]=a.z;  w0[4*m+3]=a.w;
        w1[4*m+0]=cc.x; w1[4*m+1]=cc.y; w1[4*m+2]=cc.z; w1[4*m+3]=cc.w;
        w2[4*m+0]=d.x;  w2[4*m+1]=d.y;  w2[4*m+2]=d.z;  w2[4*m+3]=d.w;
    }
    float bh0 = b_hh[lane], bh1 = b_hh[lane + 32], bh2 = b_hh[lane + 64];

    const size_t tstride = (size_t)512 * 48;
    const uint32_t* gA = gi + ((size_t)(b * 256) * 512 + n) * 48;  // seqB at +48

    #pragma unroll
    for (int s = 0; s < 7; s++) {
        const uint32_t* src = gA + (size_t)s * tstride;
        uint32_t d = (uint32_t)__cvta_generic_to_shared(&gbuf[wr][s][0]);
        cp4(d + lane * 4,         src + lane);
        cp4(d + (32 + lane) * 4,  src + 32 + lane);
        cp4(d + (64 + lane) * 4,  src + 64 + lane);
        asm volatile("cp.async.commit_group;" ::: "memory");
    }

    float hA = 0.f, hB = 0.f;
    ull hp = 0;
    float* outp = out + ((size_t)(b * 256) * 512 + n) * 32 + lane;

    for (int t = 0; t < 256; t++) {
        if (t + 7 < 256) {
            const uint32_t* src = gA + (size_t)(t + 7) * tstride;
            uint32_t d = (uint32_t)__cvta_generic_to_shared(&gbuf[wr][(t + 7) & 7][0]);
            cp4(d + lane * 4,         src + lane);
            cp4(d + (32 + lane) * 4,  src + 32 + lane);
            cp4(d + (64 + lane) * 4,  src + 64 + lane);
        }
        asm volatile("cp.async.commit_group;" ::: "memory");
        asm volatile("cp.async.wait_group 7;" ::: "memory");

        int s = t & 7;
        uint32_t sA01 = gbuf[wr][s][lane];
        uint32_t sA2  = gbuf[wr][s][32 + (lane >> 1)];
        uint32_t sB01 = gbuf[wr][s][48 + lane];
        uint32_t sB2  = gbuf[wr][s][48 + 32 + (lane >> 1)];
        float2 qA01 = __half22float2(*(const __half2*)&sA01);
        float2 qB01 = __half22float2(*(const __half2*)&sB01);
        __half2 hA2 = *(const __half2*)&sA2;
        __half2 hB2 = *(const __half2*)&sB2;
        float qA2 = (lane & 1) ? __high2float(hA2) : __low2float(hA2);
        float qB2 = (lane & 1) ? __high2float(hB2) : __low2float(hB2);

        float a0A = bh0, a1A = bh1, a2A = bh2;
        float a0B = bh0, a1B = bh1, a2B = bh2;
        float e0A = 0.f, e1A = 0.f, e2A = 0.f;
        float e0B = 0.f, e1B = 0.f, e2B = 0.f;
        #pragma unroll
        for (int jj = 0; jj < 16; jj++) {
            float2 hj = unpack2(__shfl_sync(0xffffffffu, hp, jj));
            float2 hk = unpack2(__shfl_sync(0xffffffffu, hp, jj + 16));
            a0A = fmaf(hj.x, w0[jj], a0A);       a0B = fmaf(hj.y, w0[jj], a0B);
            e0A = fmaf(hk.x, w0[jj + 16], e0A);  e0B = fmaf(hk.y, w0[jj + 16], e0B);
            a1A = fmaf(hj.x, w1[jj], a1A);       a1B = fmaf(hj.y, w1[jj], a1B);
            e1A = fmaf(hk.x, w1[jj + 16], e1A);  e1B = fmaf(hk.y, w1[jj + 16], e1B);
            a2A = fmaf(hj.x, w2[jj], a2A);       a2B = fmaf(hj.y, w2[jj], a2B);
            e2A = fmaf(hk.x, w2[jj + 16], e2A);  e2B = fmaf(hk.y, w2[jj + 16], e2B);
        }
        a0A += e0A; a1A += e1A; a2A += e2A;
        a0B += e0B; a1B += e1B; a2B += e2B;

        float rgA = sigmoid_f(qA01.x + a0A);
        float zgA = sigmoid_f(qA01.y + a1A);
        float ngA = tanh_f(fmaf(rgA, a2A, qA2));
        hA = fmaf(zgA, hA - ngA, ngA);

        float rgB = sigmoid_f(qB01.x + a0B);
        float zgB = sigmoid_f(qB01.y + a1B);
        float ngB = tanh_f(fmaf(rgB, a2B, qB2));
        hB = fmaf(zgB, hB - ngB, ngB);

        outp[0]  = hA;
        outp[32] = hB;
        outp += (size_t)512 * 32;

        hp = pack2(hA, hB);
    }
}

// ---------------------------------------------------------------------------
extern "C" void kernel_launch(void* const* d_in, const int* in_sizes, int n_in,
                              void* d_out, int out_size)
{
    (void)in_sizes; (void)n_in; (void)out_size;
    const float* x    = (const float*)d_in[0];
    const float* adj  = (const float*)d_in[1];
    const float* W1   = (const float*)d_in[2];
    const float* b1   = (const float*)d_in[3];
    const float* g1   = (const float*)d_in[4];
    const float* be1  = (const float*)d_in[5];
    const float* W2   = (const float*)d_in[6];
    const float* b2   = (const float*)d_in[7];
    const float* g2   = (const float*)d_in[8];
    const float* be2  = (const float*)d_in[9];
    const float* w_ih = (const float*)d_in[10];
    const float* w_hh = (const float*)d_in[11];
    const float* b_ih = (const float*)d_in[12];
    const float* b_hh = (const float*)d_in[13];
    float* out = (float*)d_out;

    __half *sph, *af, *th;
    uint32_t *gv;
    cudaGetSymbolAddress((void**)&sph, g_sph);
    cudaGetSymbolAddress((void**)&th,  g_th);
    cudaGetSymbolAddress((void**)&gv,  g_gi);
    cudaGetSymbolAddress((void**)&af,  g_adjf);

    k0_split<<<(Nn * Nn) / 256, 256>>>(adj, af);
    k1_mma<<<RTOT / 256, 256>>>(x, W1, b1, g1, be1, W2, b2, sph);
    k2_mma<<<dim3(4, BS / 4), 256>>>(af, sph, th);
    k3_mma<<<RTOT / 256, 256>>>(th, g2, be2, w_ih, b_ih, gv);
    k4_gru<<<BN / 8, 128>>>(gv, w_hh, b_hh, out);
}